// round 6
// baseline (speedup 1.0000x reference)
#include <cuda_runtime.h>
#include <math.h>

#define BB  8
#define NN1 128
#define NN2 512
#define DD  128
#define MROWS (BB * (NN1 + NN2))   // 5120 combined rows
#define R1   (BB * NN1)            // 1024 graph-1 rows
#define LDH  256                   // packed row stride [h | hA] (also proj [pA | pB])

// ---------------- static device scratch ----------------
__device__ float g_g    [MROWS * DD];
__device__ float g_hh0  [MROWS * LDH];
__device__ float g_hh1  [MROWS * LDH];
__device__ float g_Pcat [MROWS * LDH];
__device__ float g_e2   [BB * NN2 * NN2];
__device__ float g_a2   [BB * NN2 * NN2];
__device__ float g_e1   [BB * NN1 * NN1];
__device__ float g_a1   [BB * NN1 * NN1];
__device__ float g_Wcat [3 * DD * LDH];
__device__ float g_bcat [3 * LDH];
__device__ float g_Wproj[2 * DD * LDH];    // side0: graph1 rows, side1: graph2 rows
__device__ float g_bproj[LDH];
__device__ float g_ZA   [BB * NN1 * NN2];
__device__ float g_ZB   [BB * NN1 * NN2];
__device__ float g_part [BB * NN1 * 4];

// ---------------- parameterized 64x64 NN GEMM body (R4-proven) ----------------
__device__ __forceinline__ void gemm64p(const float* __restrict__ A, int lda,
                                        const float* __restrict__ B, int ldb,
                                        const float* __restrict__ bias,
                                        float* __restrict__ C, int ldc,
                                        int K, int m0, int n0) {
    __shared__ float As[16][68];
    __shared__ float Bs[16][68];
    int tid = threadIdx.x;
    int tx = tid & 15, ty = tid >> 4;
    int lm = tid >> 2, lkq = (tid & 3) * 4;
    int lk = tid >> 4, ln = (tid & 15) * 4;
    float acc[4][4] = {};
    for (int k0 = 0; k0 < K; k0 += 16) {
        float4 a4 = *(const float4*)&A[(long)(m0 + lm) * lda + k0 + lkq];
        As[lkq + 0][lm] = a4.x; As[lkq + 1][lm] = a4.y;
        As[lkq + 2][lm] = a4.z; As[lkq + 3][lm] = a4.w;
        *(float4*)&Bs[lk][ln] = *(const float4*)&B[(long)(k0 + lk) * ldb + n0 + ln];
        __syncthreads();
        #pragma unroll
        for (int k = 0; k < 16; k++) {
            float4 av = *(float4*)&As[k][ty * 4];
            float4 bv = *(float4*)&Bs[k][tx * 4];
            float am[4] = {av.x, av.y, av.z, av.w};
            float bn_[4] = {bv.x, bv.y, bv.z, bv.w};
            #pragma unroll
            for (int i = 0; i < 4; i++)
                #pragma unroll
                for (int j = 0; j < 4; j++)
                    acc[i][j] += am[i] * bn_[j];
        }
        __syncthreads();
    }
    #pragma unroll
    for (int i = 0; i < 4; i++) {
        int m = m0 + ty * 4 + i, n = n0 + tx * 4;
        float4 v;
        v.x = acc[i][0] + (bias ? bias[n + 0] : 0.f);
        v.y = acc[i][1] + (bias ? bias[n + 1] : 0.f);
        v.z = acc[i][2] + (bias ? bias[n + 2] : 0.f);
        v.w = acc[i][3] + (bias ? bias[n + 3] : 0.f);
        *(float4*)&C[(long)m * ldc + n] = v;
    }
}

// ---------------- parameterized 64x64 NT GEMM body ----------------
__device__ __forceinline__ void gemm64nt(const float* __restrict__ A, int lda,
                                         const float* __restrict__ B, int ldb,
                                         float* __restrict__ C, int ldc,
                                         int K, int m0, int n0) {
    __shared__ float As[16][68];
    __shared__ float Bs[16][68];
    int tid = threadIdx.x;
    int tx = tid & 15, ty = tid >> 4;
    int lm = tid >> 2, lkq = (tid & 3) * 4;
    float acc[4][4] = {};
    for (int k0 = 0; k0 < K; k0 += 16) {
        float4 a4 = *(const float4*)&A[(long)(m0 + lm) * lda + k0 + lkq];
        As[lkq + 0][lm] = a4.x; As[lkq + 1][lm] = a4.y;
        As[lkq + 2][lm] = a4.z; As[lkq + 3][lm] = a4.w;
        float4 b4 = *(const float4*)&B[(long)(n0 + lm) * ldb + k0 + lkq];
        Bs[lkq + 0][lm] = b4.x; Bs[lkq + 1][lm] = b4.y;
        Bs[lkq + 2][lm] = b4.z; Bs[lkq + 3][lm] = b4.w;
        __syncthreads();
        #pragma unroll
        for (int k = 0; k < 16; k++) {
            float4 av = *(float4*)&As[k][ty * 4];
            float4 bv = *(float4*)&Bs[k][tx * 4];
            float am[4] = {av.x, av.y, av.z, av.w};
            float bn_[4] = {bv.x, bv.y, bv.z, bv.w};
            #pragma unroll
            for (int i = 0; i < 4; i++)
                #pragma unroll
                for (int j = 0; j < 4; j++)
                    acc[i][j] += am[i] * bn_[j];
        }
        __syncthreads();
    }
    #pragma unroll
    for (int i = 0; i < 4; i++) {
        int m = m0 + ty * 4 + i, n = n0 + tx * 4;
        float4 v = {acc[i][0], acc[i][1], acc[i][2], acc[i][3]};
        *(float4*)&C[(long)m * ldc + n] = v;
    }
}

// ---------------- merged weight-prep kernel (72 role-dispatched blocks) ----------------
__global__ void k_prep(const float* __restrict__ gat_W, const float* __restrict__ gat_A,
                       const float* __restrict__ gat_b,
                       const float* __restrict__ vdwA_W1, const float* __restrict__ vdwB_W1,
                       const float* __restrict__ vdwA_b1, const float* __restrict__ vdwB_b1,
                       float* __restrict__ Wcat, float* __restrict__ bcat,
                       float* __restrict__ Wproj, float* __restrict__ bproj) {
    int bx = blockIdx.x, tid = threadIdx.x;
    if (bx < 12) {                 // Wcat[:,128:256] = W @ A
        int l = bx >> 2, t = bx & 3;
        gemm64p(gat_W + (long)l * DD * DD, DD, gat_A + (long)l * DD * DD, DD, nullptr,
                Wcat + (long)l * DD * LDH + 128, LDH, DD, (t >> 1) * 64, (t & 1) * 64);
    } else if (bx < 36) {          // Wcat[:,0:128] = W
        int idx = (bx - 12) * 2048 + tid * 8;
        int l = idx >> 14, rr = idx & 16383;
        int k = rr >> 7, n = rr & 127;
        float4 s0 = *(const float4*)&gat_W[idx];
        float4 s1 = *(const float4*)&gat_W[idx + 4];
        float* d = &Wcat[(long)l * DD * LDH + (long)k * LDH + n];
        *(float4*)d = s0; *(float4*)(d + 4) = s1;
    } else if (bx < 68) {          // Wproj[side][k][0:128|128:256] = A_W1 | B_W1 rows
        int idx = (bx - 36) * 2048 + tid * 8;
        int side = idx >> 15, rr = idx & 32767;
        int k = rr >> 8, n = rr & 255;
        const float* src = (n < 128)
            ? &vdwA_W1[(long)(side * 128 + k) * 128 + n]
            : &vdwB_W1[(long)(side * 128 + k) * 128 + n - 128];
        float4 s0 = *(const float4*)src;
        float4 s1 = *(const float4*)(src + 4);
        float* d = &Wproj[(long)side * DD * LDH + (long)k * LDH + n];
        *(float4*)d = s0; *(float4*)(d + 4) = s1;
    } else if (bx < 71) {          // bcat = [b | b@A]
        int l = bx - 68;
        if (tid < 128) {
            float acc = 0.f;
            #pragma unroll 8
            for (int k = 0; k < DD; k++)
                acc += gat_b[l * DD + k] * gat_A[((long)l * DD + k) * DD + tid];
            bcat[l * LDH + tid] = gat_b[l * DD + tid];
            bcat[l * LDH + 128 + tid] = acc;
        }
    } else {                       // bproj = [bA1 | bB1]
        if (tid < 128) {
            bproj[tid] = vdwA_b1[tid];
            bproj[128 + tid] = vdwB_b1[tid];
        }
    }
}

// embedding for both graphs
__global__ void k_embed_both(const float* __restrict__ X1, const float* __restrict__ X2,
                             const float* __restrict__ W, float* __restrict__ Y) {
    int bn = blockIdx.x;
    const float* src = (bn < R1) ? X1 + (size_t)bn * 54
                                 : X2 + (size_t)(bn - R1) * 54;
    __shared__ float xs[54];
    if (threadIdx.x < 54) xs[threadIdx.x] = src[threadIdx.x];
    __syncthreads();
    int d = threadIdx.x;
    float acc = 0.f;
    #pragma unroll
    for (int l = 0; l < 54; l++) acc += xs[l] * W[l * DD + d];
    Y[(size_t)bn * DD + d] = acc;
}

// layer-0 dual: hhA = g @ Wcat0 + bcat0  (M=5120, N=256)
__global__ void k_dual0(const float* __restrict__ g, const float* __restrict__ Wcat,
                        const float* __restrict__ bcat, float* __restrict__ hhA) {
    gemm64p(g, DD, Wcat, LDH, bcat, hhA, LDH, DD, blockIdx.y * 64, blockIdx.x * 64);
}

// e = hA @ h^T per batch; packed hhA rows [h | hA], ld = LDH
__global__ void k_nt_both(const float* __restrict__ hhA, float* __restrict__ e2,
                          float* __restrict__ e1) {
    int z = blockIdx.z;
    if (z < 8) {
        const float* base = hhA + ((long)R1 + (long)z * NN2) * LDH;
        gemm64nt(base + 128, LDH, base, LDH, e2 + (long)z * NN2 * NN2, NN2, DD,
                 blockIdx.y * 64, blockIdx.x * 64);
    } else {
        if (blockIdx.x >= 2 || blockIdx.y >= 2) return;
        const float* base = hhA + (long)(z - 8) * NN1 * LDH;
        gemm64nt(base + 128, LDH, base, LDH, e1 + (long)(z - 8) * NN1 * NN1, NN1, DD,
                 blockIdx.y * 64, blockIdx.x * 64);
    }
}

// fused symmetrize + mask + column softmax (axis=1), both graphs
__global__ void k_softmax_both(const float* __restrict__ e2, const float* __restrict__ adj2,
                               float* __restrict__ a2, const float* __restrict__ e1,
                               const float* __restrict__ adj1, float* __restrict__ a1) {
    extern __shared__ float Ls[];   // N*33 floats
    __shared__ float Ts[32][33];
    __shared__ float red[8][33];
    int z = blockIdx.y;
    int N; const float* Eb; const float* Ab; float* Ob;
    if (z < 8) {
        N = NN2;
        Eb = e2 + (long)z * NN2 * NN2; Ab = adj2 + (long)z * NN2 * NN2;
        Ob = a2 + (long)z * NN2 * NN2;
    } else {
        if (blockIdx.x >= NN1 / 32) return;
        N = NN1;
        Eb = e1 + (long)(z - 8) * NN1 * NN1; Ab = adj1 + (long)(z - 8) * NN1 * NN1;
        Ob = a1 + (long)(z - 8) * NN1 * NN1;
    }
    int k0 = blockIdx.x * 32;
    int tx = threadIdx.x, ty = threadIdx.y;
    for (int i0 = 0; i0 < N; i0 += 32) {
        for (int r = ty; r < 32; r += 8)
            Ts[r][tx] = Eb[(size_t)(k0 + r) * N + i0 + tx];
        __syncthreads();
        for (int r = ty; r < 32; r += 8) {
            float d = Eb[(size_t)(i0 + r) * N + k0 + tx];
            float a = Ab[(size_t)(i0 + r) * N + k0 + tx];
            Ls[(i0 + r) * 33 + tx] = (a > 0.f) ? (d + Ts[tx][r]) : -9e15f;
        }
        __syncthreads();
    }
    float m = -3.4e38f;
    for (int i = ty; i < N; i += 8) m = fmaxf(m, Ls[i * 33 + tx]);
    red[ty][tx] = m;
    __syncthreads();
    if (ty == 0) {
        float mm = red[0][tx];
        #pragma unroll
        for (int y = 1; y < 8; y++) mm = fmaxf(mm, red[y][tx]);
        red[0][tx] = mm;
    }
    __syncthreads();
    m = red[0][tx];
    __syncthreads();
    float s = 0.f;
    for (int i = ty; i < N; i += 8) {
        float e = __expf(Ls[i * 33 + tx] - m);
        Ls[i * 33 + tx] = e;
        s += e;
    }
    red[ty][tx] = s;
    __syncthreads();
    if (ty == 0) {
        float ss = 0.f;
        #pragma unroll
        for (int y = 0; y < 8; y++) ss += red[y][tx];
        red[0][tx] = ss;
    }
    __syncthreads();
    float inv = 1.f / red[0][tx];
    for (int i = ty; i < N; i += 8)
        Ob[(size_t)i * N + k0 + tx] = Ls[i * 33 + tx] * inv;
}

// shared-memory overlay for the fused relugate kernel
struct RgPhase1 {
    float As[16][36];
    float Bs[16][132];
    float gw1[128], gw2[128];
    float redH[32][17], redX[32][17];
    float csm[32];
};
struct RgPhase2 { float Ws[16][260]; };
union RgUnion { RgPhase1 p1; RgPhase2 p2; };

// fused: hp = relu(att@h); c = sigmoid(g.gW1 + hp.gW2 + gb); g = c*g + (1-c)*hp;
// then tail GEMM on the fresh 32-row g tile:
//   PROJMODE=0: Out[row] = g@Wnext + bnext           (next layer's [h|hA])
//   PROJMODE=1: Out[row] = g@Wproj(side) (+bproj on graph1)   (pair projections)
template<int PROJMODE>
__global__ void k_relugate(const float* __restrict__ a2, const float* __restrict__ a1,
                           const float* __restrict__ hhA_in, float* __restrict__ g,
                           const float* __restrict__ gW, const float* __restrict__ gb,
                           const float* __restrict__ Wnext, const float* __restrict__ bnext,
                           float* __restrict__ Out) {
    int z = blockIdx.z;
    int M, K; const float* att; const float* Hb; float* G; long baseRow;
    if (z < 8) {
        M = NN2; K = NN2;
        att = a2 + (long)z * NN2 * NN2;
        baseRow = (long)R1 + (long)z * NN2;
    } else {
        M = NN1; K = NN1;
        att = a1 + (long)(z - 8) * NN1 * NN1;
        baseRow = (long)(z - 8) * NN1;
    }
    Hb = hhA_in + baseRow * LDH;
    G  = g + baseRow * DD;
    int m0 = blockIdx.y * 32;
    if (m0 >= M) return;

    __shared__ RgUnion u;
    __shared__ float gs[32][132];
    int tid = threadIdx.x;
    int tx = tid & 15, ty = tid >> 4;
    if (tid < DD) { u.p1.gw1[tid] = gW[tid]; u.p1.gw2[tid] = gW[DD + tid]; }
    float acc[2][8] = {};
    for (int k0 = 0; k0 < K; k0 += 16) {
        if (tid < 128) {
            int ar = tid >> 2, akq = (tid & 3) * 4;
            float4 a4 = *(const float4*)&att[(long)(m0 + ar) * K + k0 + akq];
            u.p1.As[akq + 0][ar] = a4.x; u.p1.As[akq + 1][ar] = a4.y;
            u.p1.As[akq + 2][ar] = a4.z; u.p1.As[akq + 3][ar] = a4.w;
        }
        int br = tid >> 4, bc = (tid & 15) * 8;
        *(float4*)&u.p1.Bs[br][bc]     = *(const float4*)&Hb[(long)(k0 + br) * LDH + bc];
        *(float4*)&u.p1.Bs[br][bc + 4] = *(const float4*)&Hb[(long)(k0 + br) * LDH + bc + 4];
        __syncthreads();
        #pragma unroll
        for (int k = 0; k < 16; k++) {
            float2 av = *(float2*)&u.p1.As[k][ty * 2];
            float am[2] = {av.x, av.y};
            float4 b0 = *(float4*)&u.p1.Bs[k][tx * 8];
            float4 b1 = *(float4*)&u.p1.Bs[k][tx * 8 + 4];
            float bn_[8] = {b0.x, b0.y, b0.z, b0.w, b1.x, b1.y, b1.z, b1.w};
            #pragma unroll
            for (int i = 0; i < 2; i++)
                #pragma unroll
                for (int j = 0; j < 8; j++)
                    acc[i][j] += am[i] * bn_[j];
        }
        __syncthreads();
    }
    float xv[2][8];
    #pragma unroll
    for (int i = 0; i < 2; i++) {
        int m = m0 + ty * 2 + i;
        float4 x0 = *(const float4*)&G[(long)m * DD + tx * 8];
        float4 x1 = *(const float4*)&G[(long)m * DD + tx * 8 + 4];
        xv[i][0] = x0.x; xv[i][1] = x0.y; xv[i][2] = x0.z; xv[i][3] = x0.w;
        xv[i][4] = x1.x; xv[i][5] = x1.y; xv[i][6] = x1.z; xv[i][7] = x1.w;
    }
    #pragma unroll
    for (int i = 0; i < 2; i++) {
        float sh = 0.f, sx = 0.f;
        #pragma unroll
        for (int j = 0; j < 8; j++) {
            acc[i][j] = fmaxf(acc[i][j], 0.f);
            sh += acc[i][j] * u.p1.gw2[tx * 8 + j];
            sx += xv[i][j] * u.p1.gw1[tx * 8 + j];
        }
        u.p1.redH[ty * 2 + i][tx] = sh;
        u.p1.redX[ty * 2 + i][tx] = sx;
    }
    __syncthreads();
    if (tid < 32) {
        float s = 0.f;
        #pragma unroll
        for (int t = 0; t < 16; t++) s += u.p1.redH[tid][t] + u.p1.redX[tid][t];
        s += gb[0];
        u.p1.csm[tid] = 1.f / (1.f + __expf(-s));
    }
    __syncthreads();
    #pragma unroll
    for (int i = 0; i < 2; i++) {
        int ml = ty * 2 + i;
        int m = m0 + ml;
        float c = u.p1.csm[ml];
        float v[8];
        #pragma unroll
        for (int j = 0; j < 8; j++) {
            v[j] = c * xv[i][j] + (1.f - c) * acc[i][j];
            gs[ml][tx * 8 + j] = v[j];
        }
        float4 v0 = {v[0], v[1], v[2], v[3]};
        float4 v1 = {v[4], v[5], v[6], v[7]};
        *(float4*)&G[(long)m * DD + tx * 8]     = v0;
        *(float4*)&G[(long)m * DD + tx * 8 + 4] = v1;
    }
    __syncthreads();   // phase1 smem dead; gs ready

    // ---- fused tail: Out[32 x 256] = gs @ Wnext (+bias) ----
    const float* Wsel = Wnext;
    const float* bsel = bnext;
    if (PROJMODE) {
        Wsel = Wnext + (long)(z < 8 ? 1 : 0) * DD * LDH;
        bsel = (z >= 8) ? bnext : nullptr;
    }
    int rg = tid >> 5;            // 0..7 -> rows rg*4..rg*4+3
    int cg = (tid & 31) * 8;      // 0..248
    float acc2[4][8] = {};
    for (int c0 = 0; c0 < DD; c0 += 16) {
        int wr = tid >> 4, wc = (tid & 15) * 16;
        #pragma unroll
        for (int q = 0; q < 4; q++)
            *(float4*)&u.p2.Ws[wr][wc + q * 4] =
                *(const float4*)&Wsel[(long)(c0 + wr) * LDH + wc + q * 4];
        __syncthreads();
        #pragma unroll
        for (int k = 0; k < 16; k++) {
            float a0 = gs[rg * 4 + 0][c0 + k];
            float a1 = gs[rg * 4 + 1][c0 + k];
            float a2v = gs[rg * 4 + 2][c0 + k];
            float a3 = gs[rg * 4 + 3][c0 + k];
            float4 w0 = *(float4*)&u.p2.Ws[k][cg];
            float4 w1 = *(float4*)&u.p2.Ws[k][cg + 4];
            float w[8] = {w0.x, w0.y, w0.z, w0.w, w1.x, w1.y, w1.z, w1.w};
            #pragma unroll
            for (int j = 0; j < 8; j++) {
                acc2[0][j] += a0 * w[j];
                acc2[1][j] += a1 * w[j];
                acc2[2][j] += a2v * w[j];
                acc2[3][j] += a3 * w[j];
            }
        }
        __syncthreads();
    }
    #pragma unroll
    for (int i = 0; i < 4; i++) {
        long row = baseRow + m0 + rg * 4 + i;
        float4 o0, o1;
        o0.x = acc2[i][0] + (bsel ? bsel[cg + 0] : 0.f);
        o0.y = acc2[i][1] + (bsel ? bsel[cg + 1] : 0.f);
        o0.z = acc2[i][2] + (bsel ? bsel[cg + 2] : 0.f);
        o0.w = acc2[i][3] + (bsel ? bsel[cg + 3] : 0.f);
        o1.x = acc2[i][4] + (bsel ? bsel[cg + 4] : 0.f);
        o1.y = acc2[i][5] + (bsel ? bsel[cg + 5] : 0.f);
        o1.z = acc2[i][6] + (bsel ? bsel[cg + 6] : 0.f);
        o1.w = acc2[i][7] + (bsel ? bsel[cg + 7] : 0.f);
        *(float4*)&Out[row * LDH + cg]     = o0;
        *(float4*)&Out[row * LDH + cg + 4] = o1;
    }
}

// Z[b,i,j] = act( b2 + sum_h relu(P1[i,h]+P2[j,h]) * w2[h] ), packed Pcat (ld 256)
__global__ void k_zmat(const float* __restrict__ Pcat,
                       const float* __restrict__ w2A, const float* __restrict__ w2B,
                       const float* __restrict__ b2A, const float* __restrict__ b2B,
                       float* __restrict__ ZA, float* __restrict__ ZB) {
    __shared__ float P1s[DD][33];
    __shared__ float P2s[DD][33];
    __shared__ float w2s[DD];
    int z = blockIdx.z;
    int b = z >> 1, mlp = z & 1;
    int off = mlp ? 128 : 0;
    const float* P1 = Pcat + (long)b * NN1 * LDH + off;
    const float* P2 = Pcat + ((long)R1 + (long)b * NN2) * LDH + off;
    const float* w2 = mlp ? w2B : w2A;
    float b2 = mlp ? b2B[0] : b2A[0];
    float* Z = (mlp ? ZB : ZA) + (long)b * NN1 * NN2;
    int i0 = blockIdx.y * 32, j0 = blockIdx.x * 32;
    int tid = threadIdx.x;
    if (tid < DD) w2s[tid] = w2[tid];
    {
        int row = tid >> 3, cb = (tid & 7) * 16;
        #pragma unroll
        for (int q = 0; q < 4; q++) {
            float4 v1 = *(const float4*)&P1[(long)(i0 + row) * LDH + cb + q * 4];
            float4 v2 = *(const float4*)&P2[(long)(j0 + row) * LDH + cb + q * 4];
            P1s[cb + q * 4 + 0][row] = v1.x; P1s[cb + q * 4 + 1][row] = v1.y;
            P1s[cb + q * 4 + 2][row] = v1.z; P1s[cb + q * 4 + 3][row] = v1.w;
            P2s[cb + q * 4 + 0][row] = v2.x; P2s[cb + q * 4 + 1][row] = v2.y;
            P2s[cb + q * 4 + 2][row] = v2.z; P2s[cb + q * 4 + 3][row] = v2.w;
        }
    }
    __syncthreads();
    int tx = tid & 15, ty = tid >> 4;
    float a00 = 0.f, a01 = 0.f, a10 = 0.f, a11 = 0.f;
    #pragma unroll 4
    for (int k = 0; k < DD; k++) {
        float w = w2s[k];
        float p0 = P1s[k][ty], p1 = P1s[k][ty + 16];
        float q0 = P2s[k][tx], q1 = P2s[k][tx + 16];
        a00 += fmaxf(p0 + q0, 0.f) * w;
        a01 += fmaxf(p0 + q1, 0.f) * w;
        a10 += fmaxf(p1 + q0, 0.f) * w;
        a11 += fmaxf(p1 + q1, 0.f) * w;
    }
    a00 += b2; a01 += b2; a10 += b2; a11 += b2;
    if (mlp == 0) {
        a00 = 1.f / (1.f + __expf(-a00)); a01 = 1.f / (1.f + __expf(-a01));
        a10 = 1.f / (1.f + __expf(-a10)); a11 = 1.f / (1.f + __expf(-a11));
    } else {
        a00 = tanhf(a00) * 0.2f; a01 = tanhf(a01) * 0.2f;
        a10 = tanhf(a10) * 0.2f; a11 = tanhf(a11) * 0.2f;
    }
    Z[(long)(i0 + ty) * NN2 + j0 + tx]           = a00;
    Z[(long)(i0 + ty) * NN2 + j0 + tx + 16]      = a01;
    Z[(long)(i0 + ty + 16) * NN2 + j0 + tx]      = a10;
    Z[(long)(i0 + ty + 16) * NN2 + j0 + tx + 16] = a11;
}

// elementwise physics + per-(b,i) reduction
__global__ void k_phys(const float* __restrict__ ZA, const float* __restrict__ ZB,
                       const float* __restrict__ pos1, const float* __restrict__ pos2,
                       const float* __restrict__ r1, const float* __restrict__ r2,
                       const float* __restrict__ nm1, const float* __restrict__ nm2,
                       const float* __restrict__ A_int, float* __restrict__ part) {
    int b = blockIdx.x >> 7, i = blockIdx.x & 127;
    int t = threadIdx.x;
    float px = pos1[(b * NN1 + i) * 3 + 0];
    float py = pos1[(b * NN1 + i) * 3 + 1];
    float pz = pos1[(b * NN1 + i) * 3 + 2];
    float rr1 = r1[b * NN1 + i];
    float m1  = nm1[b * NN1 + i];
    size_t zbase = (size_t)b * NN1 * NN2 + (size_t)i * NN2;
    size_t abase = (size_t)b * 8 * NN1 * NN2 + (size_t)i * NN2;
    const size_t chw = (size_t)NN1 * NN2;
    float s0 = 0.f, s1 = 0.f, s2 = 0.f, s3 = 0.f;
    for (int j = t; j < NN2; j += 128) {
        float Aw = ZA[zbase + j];
        float Bw = ZB[zbase + j];
        float dx = px - pos2[(b * NN2 + j) * 3 + 0];
        float dy = py - pos2[(b * NN2 + j) * 3 + 1];
        float dz = pz - pos2[(b * NN2 + j) * 3 + 2];
        float dm = sqrtf(dx * dx + dy * dy + dz * dz + 1e-10f);
        if (dm < 0.5f) dm = 1e10f;
        float dm0 = rr1 + r2[b * NN2 + j] + Bw;
        float dm0s = (dm0 < 1e-4f) ? 1.f : dm0;
        float rq = dm0s / dm;
        float rq2 = rq * rq;
        float r6 = rq2 * rq2 * rq2;
        float evdw = fminf(r6 * r6 - 2.f * r6, 100.f);
        float Aamp = Aw * (0.0356f - 0.0178f) + 0.0178f;
        s0 += Aamp * evdw * m1 * nm2[b * NN2 + j];
        float dmd = dm - dm0;
        float a1 = A_int[abase + 1 * chw + j];
        float a7 = A_int[abase + 7 * chw + j];
        float a6 = A_int[abase + 6 * chw + j];
        s1 += fminf(fmaxf(dmd * a1 * (-1.f / 0.7f), 0.f), 1.f);
        s2 += fminf(fmaxf(dmd * a7 * (-1.f / 0.7f), 0.f), 1.f);
        s3 += fminf(fmaxf((1.5f - dmd) * a6, 0.f), 1.f);
    }
    #pragma unroll
    for (int o = 16; o > 0; o >>= 1) {
        s0 += __shfl_down_sync(0xffffffffu, s0, o);
        s1 += __shfl_down_sync(0xffffffffu, s1, o);
        s2 += __shfl_down_sync(0xffffffffu, s2, o);
        s3 += __shfl_down_sync(0xffffffffu, s3, o);
    }
    __shared__ float acc[4][4];
    int lane = t & 31, w = t >> 5;
    if (lane == 0) { acc[w][0] = s0; acc[w][1] = s1; acc[w][2] = s2; acc[w][3] = s3; }
    __syncthreads();
    if (t < 4)
        part[((size_t)b * NN1 + i) * 4 + t] = acc[0][t] + acc[1][t] + acc[2][t] + acc[3][t];
}

__global__ void k_final(const float* __restrict__ part, const float* __restrict__ rotor,
                        const float* __restrict__ duff, const float* __restrict__ hbc,
                        const float* __restrict__ hyc, const float* __restrict__ vdc,
                        const float* __restrict__ rtc, float* __restrict__ out) {
    int b = blockIdx.x, t = threadIdx.x;
    size_t base = ((size_t)b * NN1 + t) * 4;
    float v0 = part[base + 0], v1 = part[base + 1], v2 = part[base + 2], v3 = part[base + 3];
    #pragma unroll
    for (int o = 16; o > 0; o >>= 1) {
        v0 += __shfl_down_sync(0xffffffffu, v0, o);
        v1 += __shfl_down_sync(0xffffffffu, v1, o);
        v2 += __shfl_down_sync(0xffffffffu, v2, o);
        v3 += __shfl_down_sync(0xffffffffu, v3, o);
    }
    __shared__ float red[4][4];
    if ((t & 31) == 0) {
        int w = t >> 5;
        red[w][0] = v0; red[w][1] = v1; red[w][2] = v2; red[w][3] = v3;
    }
    __syncthreads();
    if (t == 0) {
        float s0 = red[0][0] + red[1][0] + red[2][0] + red[3][0];
        float s1 = red[0][1] + red[1][1] + red[2][1] + red[3][1];
        float s2 = red[0][2] + red[1][2] + red[2][2] + red[3][2];
        float s3 = red[0][3] + red[1][3] + red[2][3] + red[3][3];
        float hb = -hbc[0] * hbc[0];
        float hy = -hyc[0] * hyc[0];
        float inv = 1.f / (1.f + rtc[0] * rtc[0] * rotor[b]);
        out[b * 5 + 0] = s0 * inv;
        out[b * 5 + 1] = s1 * hb * inv;
        out[b * 5 + 2] = s2 * hb * inv;
        out[b * 5 + 3] = s3 * hy * inv;
        out[b * 5 + 4] = duff[b] * vdc[0] * vdc[0] * inv;
    }
}

// ---------------- host side ----------------
extern "C" void kernel_launch(void* const* d_in, const int* in_sizes, int n_in,
                              void* d_out, int out_size) {
    (void)in_sizes; (void)n_in; (void)out_size;
    const float* h1      = (const float*)d_in[0];
    const float* adj1    = (const float*)d_in[1];
    const float* h2      = (const float*)d_in[2];
    const float* adj2    = (const float*)d_in[3];
    const float* A_int   = (const float*)d_in[4];
    const float* pos1    = (const float*)d_in[5];
    const float* pos2    = (const float*)d_in[6];
    const float* rotor   = (const float*)d_in[7];
    const float* vdw_r1  = (const float*)d_in[8];
    const float* vdw_r2  = (const float*)d_in[9];
    const float* duff    = (const float*)d_in[10];
    const float* nm1     = (const float*)d_in[11];
    const float* nm2     = (const float*)d_in[12];
    const float* node_W  = (const float*)d_in[13];
    const float* gat_W   = (const float*)d_in[14];
    const float* gat_b   = (const float*)d_in[15];
    const float* gat_A   = (const float*)d_in[16];
    const float* gate_W  = (const float*)d_in[17];
    const float* gate_b  = (const float*)d_in[18];
    const float* vdwA_W1 = (const float*)d_in[19];
    const float* vdwA_b1 = (const float*)d_in[20];
    const float* vdwA_W2 = (const float*)d_in[21];
    const float* vdwA_b2 = (const float*)d_in[22];
    const float* vdwB_W1 = (const float*)d_in[23];
    const float* vdwB_b1 = (const float*)d_in[24];
    const float* vdwB_W2 = (const float*)d_in[25];
    const float* vdwB_b2 = (const float*)d_in[26];
    const float* hbond   = (const float*)d_in[27];
    const float* hydro   = (const float*)d_in[28];
    const float* vdwc    = (const float*)d_in[29];
    const float* rotc    = (const float*)d_in[30];
    float* out = (float*)d_out;

    float *gp, *hh0, *hh1, *pcat, *e2p, *a2p, *e1p, *a1p;
    float *wcp, *bcp, *wpp, *bpp, *zap, *zbp, *partp;
    cudaGetSymbolAddress((void**)&gp,   g_g);
    cudaGetSymbolAddress((void**)&hh0,  g_hh0);
    cudaGetSymbolAddress((void**)&hh1,  g_hh1);
    cudaGetSymbolAddress((void**)&pcat, g_Pcat);
    cudaGetSymbolAddress((void**)&e2p,  g_e2);
    cudaGetSymbolAddress((void**)&a2p,  g_a2);
    cudaGetSymbolAddress((void**)&e1p,  g_e1);
    cudaGetSymbolAddress((void**)&a1p,  g_a1);
    cudaGetSymbolAddress((void**)&wcp,  g_Wcat);
    cudaGetSymbolAddress((void**)&bcp,  g_bcat);
    cudaGetSymbolAddress((void**)&wpp,  g_Wproj);
    cudaGetSymbolAddress((void**)&bpp,  g_bproj);
    cudaGetSymbolAddress((void**)&zap,  g_ZA);
    cudaGetSymbolAddress((void**)&zbp,  g_ZB);
    cudaGetSymbolAddress((void**)&partp, g_part);

    (void)cudaFuncSetAttribute(k_softmax_both,
                               cudaFuncAttributeMaxDynamicSharedMemorySize,
                               NN2 * 33 * 4);

    // 1. merged weight prep + embedding + layer-0 dual
    k_prep<<<72, 256>>>(gat_W, gat_A, gat_b, vdwA_W1, vdwB_W1, vdwA_b1, vdwB_b1,
                        wcp, bcp, wpp, bpp);
    k_embed_both<<<MROWS, DD>>>(h1, h2, node_W, gp);
    k_dual0<<<dim3(4, MROWS / 64), 256>>>(gp, wcp, bcp, hh0);

    // 2. GAT layers (dual of next layer / projections fused into relugate tail)
    float* bufs[2] = {hh0, hh1};
    for (int l = 0; l < 3; l++) {
        float* hin  = bufs[l & 1];
        float* hout = bufs[(l + 1) & 1];
        const float* gW = gate_W + (size_t)l * 2 * DD;
        const float* gb = gate_b + l;
        k_nt_both<<<dim3(8, 8, 16), 256>>>(hin, e2p, e1p);
        k_softmax_both<<<dim3(16, 16), dim3(32, 8), NN2 * 33 * 4>>>(e2p, adj2, a2p,
                                                                    e1p, adj1, a1p);
        if (l < 2) {
            k_relugate<0><<<dim3(1, 16, 16), 256>>>(a2p, a1p, hin, gp, gW, gb,
                                                    wcp + (size_t)(l + 1) * DD * LDH,
                                                    bcp + (size_t)(l + 1) * LDH, hout);
        } else {
            k_relugate<1><<<dim3(1, 16, 16), 256>>>(a2p, a1p, hin, gp, gW, gb,
                                                    wpp, bpp, pcat);
        }
    }

    // 3. pair bilinear-relu MLP matrices
    k_zmat<<<dim3(16, 4, 16), 256>>>(pcat, vdwA_W2, vdwB_W2, vdwA_b2, vdwB_b2,
                                     zap, zbp);
    // 4. physics + reductions
    k_phys<<<BB * NN1, 128>>>(zap, zbp, pos1, pos2, vdw_r1, vdw_r2, nm1, nm2,
                              A_int, partp);
    k_final<<<BB, 128>>>(partp, rotor, duff, hbond, hydro, vdwc, rotc, out);
}

// round 7
// speedup vs baseline: 1.0363x; 1.0363x over previous
#include <cuda_runtime.h>
#include <math.h>

#define BB  8
#define NN1 128
#define NN2 512
#define DD  128
#define MROWS (BB * (NN1 + NN2))   // 5120 combined rows
#define R1   (BB * NN1)            // 1024 graph-1 rows

// ---------------- static device scratch ----------------
__device__ float g_g  [MROWS * DD];
__device__ float g_h  [MROWS * DD];
__device__ float g_hA [MROWS * DD];
__device__ float g_e2 [BB * NN2 * NN2];
__device__ float g_a2 [BB * NN2 * NN2];
__device__ float g_e1 [BB * NN1 * NN1];
__device__ float g_a1 [BB * NN1 * NN1];
__device__ float g_WA [3 * DD * DD];
__device__ float g_bA [3 * DD];
__device__ float g_P1A[BB * NN1 * DD];
__device__ float g_P1B[BB * NN1 * DD];
__device__ float g_P2A[BB * NN2 * DD];
__device__ float g_P2B[BB * NN2 * DD];
__device__ float g_ZA [BB * NN1 * NN2];
__device__ float g_ZB [BB * NN1 * NN2];
__device__ float g_part[BB * NN1 * 4];

// ---------------- packed f32x2 helpers (Blackwell FFMA2) ----------------
__device__ __forceinline__ unsigned long long pk2(float x, float y) {
    unsigned long long r;
    asm("mov.b64 %0, {%1, %2};" : "=l"(r) : "f"(x), "f"(y));
    return r;
}
__device__ __forceinline__ unsigned long long dup2(float x) {
    unsigned long long r;
    asm("mov.b64 %0, {%1, %1};" : "=l"(r) : "f"(x));
    return r;
}
__device__ __forceinline__ void fma2(unsigned long long& acc, unsigned long long a,
                                     unsigned long long b) {
    asm("fma.rn.f32x2 %0, %1, %2, %0;" : "+l"(acc) : "l"(a), "l"(b));
}
__device__ __forceinline__ float2 unpk(unsigned long long v) {
    float2 r;
    asm("mov.b64 {%0, %1}, %2;" : "=f"(r.x), "=f"(r.y) : "l"(v));
    return r;
}

// ---------------- shared 64x64 GEMM body (A[M,K] @ B[K,N] + bias) ----------------
template<int RELU>
__device__ __forceinline__ void gemm64_body(const float* __restrict__ A,
                                            const float* __restrict__ B,
                                            const float* __restrict__ bias,
                                            float* __restrict__ C,
                                            int N, int K, int m0, int n0) {
    __shared__ float As[16][68];
    __shared__ float Bs[16][68];
    int tid = threadIdx.x;
    int tx = tid & 15, ty = tid >> 4;
    int lm = tid >> 2, lkq = (tid & 3) * 4;
    int lk = tid >> 4, ln = (tid & 15) * 4;
    unsigned long long accp[4][2] = {};
    for (int k0 = 0; k0 < K; k0 += 16) {
        float4 a4 = *(const float4*)&A[(long)(m0 + lm) * K + k0 + lkq];
        As[lkq + 0][lm] = a4.x; As[lkq + 1][lm] = a4.y;
        As[lkq + 2][lm] = a4.z; As[lkq + 3][lm] = a4.w;
        *(float4*)&Bs[lk][ln] = *(const float4*)&B[(long)(k0 + lk) * N + n0 + ln];
        __syncthreads();
        #pragma unroll
        for (int k = 0; k < 16; k++) {
            float4 av = *(float4*)&As[k][ty * 4];
            float4 bv = *(float4*)&Bs[k][tx * 4];
            unsigned long long b01 = pk2(bv.x, bv.y);
            unsigned long long b23 = pk2(bv.z, bv.w);
            float am[4] = {av.x, av.y, av.z, av.w};
            #pragma unroll
            for (int i = 0; i < 4; i++) {
                unsigned long long a2 = dup2(am[i]);
                fma2(accp[i][0], a2, b01);
                fma2(accp[i][1], a2, b23);
            }
        }
        __syncthreads();
    }
    #pragma unroll
    for (int i = 0; i < 4; i++) {
        int m = m0 + ty * 4 + i;
        int n = n0 + tx * 4;
        float2 c01 = unpk(accp[i][0]);
        float2 c23 = unpk(accp[i][1]);
        float4 v;
        v.x = c01.x + (bias ? bias[n + 0] : 0.f);
        v.y = c01.y + (bias ? bias[n + 1] : 0.f);
        v.z = c23.x + (bias ? bias[n + 2] : 0.f);
        v.w = c23.y + (bias ? bias[n + 3] : 0.f);
        if (RELU) {
            v.x = fmaxf(v.x, 0.f); v.y = fmaxf(v.y, 0.f);
            v.z = fmaxf(v.z, 0.f); v.w = fmaxf(v.w, 0.f);
        }
        *(float4*)&C[(long)m * N + n] = v;
    }
}

// WA[l] = gat_W[l] @ gat_A[l]
__global__ void k_wa(const float* __restrict__ W, const float* __restrict__ A,
                     float* __restrict__ WA) {
    int l = blockIdx.z;
    gemm64_body<0>(W + (long)l * DD * DD, A + (long)l * DD * DD, nullptr,
                   WA + (long)l * DD * DD, DD, DD, blockIdx.y * 64, blockIdx.x * 64);
}

// bA[l] = gat_b[l] @ gat_A[l]
__global__ void k_bvec(const float* __restrict__ b, const float* __restrict__ A,
                       float* __restrict__ bA) {
    int l = blockIdx.x, n = threadIdx.x;
    float acc = 0.f;
    #pragma unroll 8
    for (int k = 0; k < DD; k++)
        acc += b[l * DD + k] * A[((long)l * DD + k) * DD + n];
    bA[l * DD + n] = acc;
}

// embedding for both graphs
__global__ void k_embed_both(const float* __restrict__ X1, const float* __restrict__ X2,
                             const float* __restrict__ W, float* __restrict__ Y) {
    int bn = blockIdx.x;
    const float* src = (bn < R1) ? X1 + (size_t)bn * 54
                                 : X2 + (size_t)(bn - R1) * 54;
    __shared__ float xs[54];
    if (threadIdx.x < 54) xs[threadIdx.x] = src[threadIdx.x];
    __syncthreads();
    int d = threadIdx.x;
    float acc = 0.f;
    #pragma unroll
    for (int l = 0; l < 54; l++) acc += xs[l] * W[l * DD + d];
    Y[(size_t)bn * DD + d] = acc;
}

// h = g@W + b ; hA = g@WA + bA  (one launch, 5120 rows)
__global__ void k_dual(const float* __restrict__ g, const float* __restrict__ W,
                       const float* __restrict__ b, const float* __restrict__ WA,
                       const float* __restrict__ bA, float* __restrict__ h,
                       float* __restrict__ hA) {
    int xi = blockIdx.x;
    const float* B; const float* bias; float* C; int n0;
    if (xi < 2) { B = W;  bias = b;  C = h;  n0 = xi * 64; }
    else        { B = WA; bias = bA; C = hA; n0 = (xi - 2) * 64; }
    gemm64_body<0>(g, B, bias, C, DD, DD, blockIdx.y * 64, n0);
}

// e = hA @ h^T, both graphs (z<8: graph2 N=512; z>=8: graph1 N=128)
__global__ void k_nt_both(const float* __restrict__ h, const float* __restrict__ hA,
                          float* __restrict__ e2, float* __restrict__ e1) {
    int z = blockIdx.z;
    int N; const float* Ab; const float* Bb; float* Cb;
    if (z < 8) {
        N = NN2;
        Ab = hA + ((long)R1 + (long)z * NN2) * DD;
        Bb = h  + ((long)R1 + (long)z * NN2) * DD;
        Cb = e2 + (long)z * NN2 * NN2;
    } else {
        if (blockIdx.x >= 2 || blockIdx.y >= 2) return;
        N = NN1;
        Ab = hA + (long)(z - 8) * NN1 * DD;
        Bb = h  + (long)(z - 8) * NN1 * DD;
        Cb = e1 + (long)(z - 8) * NN1 * NN1;
    }
    __shared__ float As[16][68];
    __shared__ float Bs[16][68];
    int m0 = blockIdx.y * 64, n0 = blockIdx.x * 64;
    int tid = threadIdx.x;
    int tx = tid & 15, ty = tid >> 4;
    int lm = tid >> 2, lkq = (tid & 3) * 4;
    unsigned long long accp[4][2] = {};
    for (int k0 = 0; k0 < DD; k0 += 16) {
        float4 a4 = *(const float4*)&Ab[(long)(m0 + lm) * DD + k0 + lkq];
        As[lkq + 0][lm] = a4.x; As[lkq + 1][lm] = a4.y;
        As[lkq + 2][lm] = a4.z; As[lkq + 3][lm] = a4.w;
        float4 b4 = *(const float4*)&Bb[(long)(n0 + lm) * DD + k0 + lkq];
        Bs[lkq + 0][lm] = b4.x; Bs[lkq + 1][lm] = b4.y;
        Bs[lkq + 2][lm] = b4.z; Bs[lkq + 3][lm] = b4.w;
        __syncthreads();
        #pragma unroll
        for (int k = 0; k < 16; k++) {
            float4 av = *(float4*)&As[k][ty * 4];
            float4 bv = *(float4*)&Bs[k][tx * 4];
            unsigned long long b01 = pk2(bv.x, bv.y);
            unsigned long long b23 = pk2(bv.z, bv.w);
            float am[4] = {av.x, av.y, av.z, av.w};
            #pragma unroll
            for (int i = 0; i < 4; i++) {
                unsigned long long a2 = dup2(am[i]);
                fma2(accp[i][0], a2, b01);
                fma2(accp[i][1], a2, b23);
            }
        }
        __syncthreads();
    }
    #pragma unroll
    for (int i = 0; i < 4; i++) {
        int m = m0 + ty * 4 + i, n = n0 + tx * 4;
        float2 c01 = unpk(accp[i][0]);
        float2 c23 = unpk(accp[i][1]);
        float4 v = {c01.x, c01.y, c23.x, c23.y};
        *(float4*)&Cb[(long)m * N + n] = v;
    }
}

// fused symmetrize + mask + column softmax (axis=1), both graphs
__global__ void k_softmax_both(const float* __restrict__ e2, const float* __restrict__ adj2,
                               float* __restrict__ a2, const float* __restrict__ e1,
                               const float* __restrict__ adj1, float* __restrict__ a1) {
    extern __shared__ float Ls[];   // N*33 floats
    __shared__ float Ts[32][33];
    __shared__ float red[8][33];
    int z = blockIdx.y;
    int N; const float* Eb; const float* Ab; float* Ob;
    if (z < 8) {
        N = NN2;
        Eb = e2 + (long)z * NN2 * NN2; Ab = adj2 + (long)z * NN2 * NN2;
        Ob = a2 + (long)z * NN2 * NN2;
    } else {
        if (blockIdx.x >= NN1 / 32) return;
        N = NN1;
        Eb = e1 + (long)(z - 8) * NN1 * NN1; Ab = adj1 + (long)(z - 8) * NN1 * NN1;
        Ob = a1 + (long)(z - 8) * NN1 * NN1;
    }
    int k0 = blockIdx.x * 32;
    int tx = threadIdx.x, ty = threadIdx.y;
    for (int i0 = 0; i0 < N; i0 += 32) {
        for (int r = ty; r < 32; r += 8)
            Ts[r][tx] = Eb[(size_t)(k0 + r) * N + i0 + tx];
        __syncthreads();
        for (int r = ty; r < 32; r += 8) {
            float d = Eb[(size_t)(i0 + r) * N + k0 + tx];
            float a = Ab[(size_t)(i0 + r) * N + k0 + tx];
            Ls[(i0 + r) * 33 + tx] = (a > 0.f) ? (d + Ts[tx][r]) : -9e15f;
        }
        __syncthreads();
    }
    float m = -3.4e38f;
    for (int i = ty; i < N; i += 8) m = fmaxf(m, Ls[i * 33 + tx]);
    red[ty][tx] = m;
    __syncthreads();
    if (ty == 0) {
        float mm = red[0][tx];
        #pragma unroll
        for (int y = 1; y < 8; y++) mm = fmaxf(mm, red[y][tx]);
        red[0][tx] = mm;
    }
    __syncthreads();
    m = red[0][tx];
    __syncthreads();
    float s = 0.f;
    for (int i = ty; i < N; i += 8) {
        float e = __expf(Ls[i * 33 + tx] - m);
        Ls[i * 33 + tx] = e;
        s += e;
    }
    red[ty][tx] = s;
    __syncthreads();
    if (ty == 0) {
        float ss = 0.f;
        #pragma unroll
        for (int y = 0; y < 8; y++) ss += red[y][tx];
        red[0][tx] = ss;
    }
    __syncthreads();
    float inv = 1.f / red[0][tx];
    for (int i = ty; i < N; i += 8)
        Ob[(size_t)i * N + k0 + tx] = Ls[i * 33 + tx] * inv;
}

// fused: hp = relu(att @ h); c = sigmoid(g.gW1 + hp.gW2 + gb); g = c*g + (1-c)*hp
// tile 32 rows x 128 cols. z<8: graph2 (M=K=512); z>=8: graph1 (M=K=128).
__global__ void k_relugate(const float* __restrict__ a2, const float* __restrict__ a1,
                           const float* __restrict__ h, float* __restrict__ g,
                           const float* __restrict__ gW, const float* __restrict__ gb) {
    int z = blockIdx.z;
    int M, K; const float* att; const float* Hb; float* G;
    if (z < 8) {
        M = NN2; K = NN2;
        att = a2 + (long)z * NN2 * NN2;
        Hb = h + ((long)R1 + (long)z * NN2) * DD;
        G  = g + ((long)R1 + (long)z * NN2) * DD;
    } else {
        M = NN1; K = NN1;
        att = a1 + (long)(z - 8) * NN1 * NN1;
        Hb = h + (long)(z - 8) * NN1 * DD;
        G  = g + (long)(z - 8) * NN1 * DD;
    }
    int m0 = blockIdx.y * 32;
    if (m0 >= M) return;
    __shared__ float As[16][36];
    __shared__ float Bs[16][132];
    __shared__ float gw1[DD], gw2[DD];
    __shared__ float redH[32][17], redX[32][17];
    __shared__ float csm[32];
    int tid = threadIdx.x;
    int tx = tid & 15, ty = tid >> 4;
    if (tid < DD) { gw1[tid] = gW[tid]; gw2[tid] = gW[DD + tid]; }
    unsigned long long accp[2][4] = {};
    for (int k0 = 0; k0 < K; k0 += 16) {
        if (tid < 128) {
            int ar = tid >> 2, akq = (tid & 3) * 4;
            float4 a4 = *(const float4*)&att[(long)(m0 + ar) * K + k0 + akq];
            As[akq + 0][ar] = a4.x; As[akq + 1][ar] = a4.y;
            As[akq + 2][ar] = a4.z; As[akq + 3][ar] = a4.w;
        }
        int br = tid >> 4, bc = (tid & 15) * 8;
        *(float4*)&Bs[br][bc]     = *(const float4*)&Hb[(long)(k0 + br) * DD + bc];
        *(float4*)&Bs[br][bc + 4] = *(const float4*)&Hb[(long)(k0 + br) * DD + bc + 4];
        __syncthreads();
        #pragma unroll
        for (int k = 0; k < 16; k++) {
            float2 av = *(float2*)&As[k][ty * 2];
            float4 b0 = *(float4*)&Bs[k][tx * 8];
            float4 b1 = *(float4*)&Bs[k][tx * 8 + 4];
            unsigned long long p0 = pk2(b0.x, b0.y);
            unsigned long long p1 = pk2(b0.z, b0.w);
            unsigned long long p2 = pk2(b1.x, b1.y);
            unsigned long long p3 = pk2(b1.z, b1.w);
            unsigned long long a0 = dup2(av.x);
            unsigned long long a1d = dup2(av.y);
            fma2(accp[0][0], a0, p0); fma2(accp[0][1], a0, p1);
            fma2(accp[0][2], a0, p2); fma2(accp[0][3], a0, p3);
            fma2(accp[1][0], a1d, p0); fma2(accp[1][1], a1d, p1);
            fma2(accp[1][2], a1d, p2); fma2(accp[1][3], a1d, p3);
        }
        __syncthreads();
    }
    // unpack accumulators
    float acc[2][8];
    #pragma unroll
    for (int i = 0; i < 2; i++) {
        #pragma unroll
        for (int q = 0; q < 4; q++) {
            float2 c = unpk(accp[i][q]);
            acc[i][q * 2 + 0] = c.x;
            acc[i][q * 2 + 1] = c.y;
        }
    }
    float xv[2][8];
    #pragma unroll
    for (int i = 0; i < 2; i++) {
        int m = m0 + ty * 2 + i;
        float4 x0 = *(const float4*)&G[(long)m * DD + tx * 8];
        float4 x1 = *(const float4*)&G[(long)m * DD + tx * 8 + 4];
        xv[i][0] = x0.x; xv[i][1] = x0.y; xv[i][2] = x0.z; xv[i][3] = x0.w;
        xv[i][4] = x1.x; xv[i][5] = x1.y; xv[i][6] = x1.z; xv[i][7] = x1.w;
    }
    #pragma unroll
    for (int i = 0; i < 2; i++) {
        float sh = 0.f, sx = 0.f;
        #pragma unroll
        for (int j = 0; j < 8; j++) {
            acc[i][j] = fmaxf(acc[i][j], 0.f);
            sh += acc[i][j] * gw2[tx * 8 + j];
            sx += xv[i][j] * gw1[tx * 8 + j];
        }
        redH[ty * 2 + i][tx] = sh;
        redX[ty * 2 + i][tx] = sx;
    }
    __syncthreads();
    if (tid < 32) {
        float s = 0.f;
        #pragma unroll
        for (int t = 0; t < 16; t++) s += redH[tid][t] + redX[tid][t];
        s += gb[0];
        csm[tid] = 1.f / (1.f + __expf(-s));
    }
    __syncthreads();
    #pragma unroll
    for (int i = 0; i < 2; i++) {
        int m = m0 + ty * 2 + i;
        float c = csm[ty * 2 + i];
        float4 v0, v1;
        v0.x = c * xv[i][0] + (1.f - c) * acc[i][0];
        v0.y = c * xv[i][1] + (1.f - c) * acc[i][1];
        v0.z = c * xv[i][2] + (1.f - c) * acc[i][2];
        v0.w = c * xv[i][3] + (1.f - c) * acc[i][3];
        v1.x = c * xv[i][4] + (1.f - c) * acc[i][4];
        v1.y = c * xv[i][5] + (1.f - c) * acc[i][5];
        v1.z = c * xv[i][6] + (1.f - c) * acc[i][6];
        v1.w = c * xv[i][7] + (1.f - c) * acc[i][7];
        *(float4*)&G[(long)m * DD + tx * 8]     = v0;
        *(float4*)&G[(long)m * DD + tx * 8 + 4] = v1;
    }
}

// all 4 pair projections in one launch (z: 0=p1a 1=p1b 2=p2a 3=p2b)
__global__ void k_proj(const float* __restrict__ g,
                       const float* __restrict__ WA1, const float* __restrict__ bA1,
                       const float* __restrict__ WB1, const float* __restrict__ bB1,
                       float* __restrict__ p1a, float* __restrict__ p1b,
                       float* __restrict__ p2a, float* __restrict__ p2b) {
    int z = blockIdx.z;
    const float* A; const float* B; const float* bias; float* C; int mt;
    switch (z) {
        case 0: A = g;            B = WA1;           bias = bA1;   C = p1a; mt = R1 / 64; break;
        case 1: A = g;            B = WB1;           bias = bB1;   C = p1b; mt = R1 / 64; break;
        case 2: A = g + (long)R1 * DD; B = WA1 + DD * DD; bias = nullptr; C = p2a; mt = (BB * NN2) / 64; break;
        default:A = g + (long)R1 * DD; B = WB1 + DD * DD; bias = nullptr; C = p2b; mt = (BB * NN2) / 64; break;
    }
    if ((int)blockIdx.y >= mt) return;
    gemm64_body<0>(A, DD == 0 ? nullptr : B, bias, C, DD, DD, blockIdx.y * 64, blockIdx.x * 64);
}

// Z[b,i,j] = act( b2 + sum_h relu(P1[i,h]+P2[j,h]) * w2[h] ), 32x32 tiles
__global__ void k_zmat(const float* __restrict__ p1a, const float* __restrict__ p1b,
                       const float* __restrict__ p2a, const float* __restrict__ p2b,
                       const float* __restrict__ w2A, const float* __restrict__ w2B,
                       const float* __restrict__ b2A, const float* __restrict__ b2B,
                       float* __restrict__ ZA, float* __restrict__ ZB) {
    __shared__ float P1s[DD][33];
    __shared__ float P2s[DD][33];
    __shared__ float w2s[DD];
    int z = blockIdx.z;
    int b = z >> 1, mlp = z & 1;
    const float* P1 = (mlp ? p1b : p1a) + (long)b * NN1 * DD;
    const float* P2 = (mlp ? p2b : p2a) + (long)b * NN2 * DD;
    const float* w2 = mlp ? w2B : w2A;
    float b2 = mlp ? b2B[0] : b2A[0];
    float* Z = (mlp ? ZB : ZA) + (long)b * NN1 * NN2;
    int i0 = blockIdx.y * 32, j0 = blockIdx.x * 32;
    int tid = threadIdx.x;
    if (tid < DD) w2s[tid] = w2[tid];
    {
        int row = tid >> 3, cb = (tid & 7) * 16;
        #pragma unroll
        for (int q = 0; q < 4; q++) {
            float4 v1 = *(const float4*)&P1[(long)(i0 + row) * DD + cb + q * 4];
            float4 v2 = *(const float4*)&P2[(long)(j0 + row) * DD + cb + q * 4];
            P1s[cb + q * 4 + 0][row] = v1.x; P1s[cb + q * 4 + 1][row] = v1.y;
            P1s[cb + q * 4 + 2][row] = v1.z; P1s[cb + q * 4 + 3][row] = v1.w;
            P2s[cb + q * 4 + 0][row] = v2.x; P2s[cb + q * 4 + 1][row] = v2.y;
            P2s[cb + q * 4 + 2][row] = v2.z; P2s[cb + q * 4 + 3][row] = v2.w;
        }
    }
    __syncthreads();
    int tx = tid & 15, ty = tid >> 4;
    float a00 = 0.f, a01 = 0.f, a10 = 0.f, a11 = 0.f;
    #pragma unroll 4
    for (int k = 0; k < DD; k++) {
        float w = w2s[k];
        float p0 = P1s[k][ty], p1 = P1s[k][ty + 16];
        float q0 = P2s[k][tx], q1 = P2s[k][tx + 16];
        a00 += fmaxf(p0 + q0, 0.f) * w;
        a01 += fmaxf(p0 + q1, 0.f) * w;
        a10 += fmaxf(p1 + q0, 0.f) * w;
        a11 += fmaxf(p1 + q1, 0.f) * w;
    }
    a00 += b2; a01 += b2; a10 += b2; a11 += b2;
    if (mlp == 0) {
        a00 = 1.f / (1.f + __expf(-a00)); a01 = 1.f / (1.f + __expf(-a01));
        a10 = 1.f / (1.f + __expf(-a10)); a11 = 1.f / (1.f + __expf(-a11));
    } else {
        a00 = tanhf(a00) * 0.2f; a01 = tanhf(a01) * 0.2f;
        a10 = tanhf(a10) * 0.2f; a11 = tanhf(a11) * 0.2f;
    }
    Z[(long)(i0 + ty) * NN2 + j0 + tx]           = a00;
    Z[(long)(i0 + ty) * NN2 + j0 + tx + 16]      = a01;
    Z[(long)(i0 + ty + 16) * NN2 + j0 + tx]      = a10;
    Z[(long)(i0 + ty + 16) * NN2 + j0 + tx + 16] = a11;
}

// elementwise physics + per-(b,i) reduction
__global__ void k_phys(const float* __restrict__ ZA, const float* __restrict__ ZB,
                       const float* __restrict__ pos1, const float* __restrict__ pos2,
                       const float* __restrict__ r1, const float* __restrict__ r2,
                       const float* __restrict__ nm1, const float* __restrict__ nm2,
                       const float* __restrict__ A_int, float* __restrict__ part) {
    int b = blockIdx.x >> 7, i = blockIdx.x & 127;
    int t = threadIdx.x;
    float px = pos1[(b * NN1 + i) * 3 + 0];
    float py = pos1[(b * NN1 + i) * 3 + 1];
    float pz = pos1[(b * NN1 + i) * 3 + 2];
    float rr1 = r1[b * NN1 + i];
    float m1  = nm1[b * NN1 + i];
    size_t zbase = (size_t)b * NN1 * NN2 + (size_t)i * NN2;
    size_t abase = (size_t)b * 8 * NN1 * NN2 + (size_t)i * NN2;
    const size_t chw = (size_t)NN1 * NN2;
    float s0 = 0.f, s1 = 0.f, s2 = 0.f, s3 = 0.f;
    for (int j = t; j < NN2; j += 128) {
        float Aw = ZA[zbase + j];
        float Bw = ZB[zbase + j];
        float dx = px - pos2[(b * NN2 + j) * 3 + 0];
        float dy = py - pos2[(b * NN2 + j) * 3 + 1];
        float dz = pz - pos2[(b * NN2 + j) * 3 + 2];
        float dm = sqrtf(dx * dx + dy * dy + dz * dz + 1e-10f);
        if (dm < 0.5f) dm = 1e10f;
        float dm0 = rr1 + r2[b * NN2 + j] + Bw;
        float dm0s = (dm0 < 1e-4f) ? 1.f : dm0;
        float rq = dm0s / dm;
        float rq2 = rq * rq;
        float r6 = rq2 * rq2 * rq2;
        float evdw = fminf(r6 * r6 - 2.f * r6, 100.f);
        float Aamp = Aw * (0.0356f - 0.0178f) + 0.0178f;
        s0 += Aamp * evdw * m1 * nm2[b * NN2 + j];
        float dmd = dm - dm0;
        float a1 = A_int[abase + 1 * chw + j];
        float a7 = A_int[abase + 7 * chw + j];
        float a6 = A_int[abase + 6 * chw + j];
        s1 += fminf(fmaxf(dmd * a1 * (-1.f / 0.7f), 0.f), 1.f);
        s2 += fminf(fmaxf(dmd * a7 * (-1.f / 0.7f), 0.f), 1.f);
        s3 += fminf(fmaxf((1.5f - dmd) * a6, 0.f), 1.f);
    }
    #pragma unroll
    for (int o = 16; o > 0; o >>= 1) {
        s0 += __shfl_down_sync(0xffffffffu, s0, o);
        s1 += __shfl_down_sync(0xffffffffu, s1, o);
        s2 += __shfl_down_sync(0xffffffffu, s2, o);
        s3 += __shfl_down_sync(0xffffffffu, s3, o);
    }
    __shared__ float acc[4][4];
    int lane = t & 31, w = t >> 5;
    if (lane == 0) { acc[w][0] = s0; acc[w][1] = s1; acc[w][2] = s2; acc[w][3] = s3; }
    __syncthreads();
    if (t < 4)
        part[((size_t)b * NN1 + i) * 4 + t] = acc[0][t] + acc[1][t] + acc[2][t] + acc[3][t];
}

__global__ void k_final(const float* __restrict__ part, const float* __restrict__ rotor,
                        const float* __restrict__ duff, const float* __restrict__ hbc,
                        const float* __restrict__ hyc, const float* __restrict__ vdc,
                        const float* __restrict__ rtc, float* __restrict__ out) {
    int b = blockIdx.x, t = threadIdx.x;
    size_t base = ((size_t)b * NN1 + t) * 4;
    float v0 = part[base + 0], v1 = part[base + 1], v2 = part[base + 2], v3 = part[base + 3];
    #pragma unroll
    for (int o = 16; o > 0; o >>= 1) {
        v0 += __shfl_down_sync(0xffffffffu, v0, o);
        v1 += __shfl_down_sync(0xffffffffu, v1, o);
        v2 += __shfl_down_sync(0xffffffffu, v2, o);
        v3 += __shfl_down_sync(0xffffffffu, v3, o);
    }
    __shared__ float red[4][4];
    if ((t & 31) == 0) {
        int w = t >> 5;
        red[w][0] = v0; red[w][1] = v1; red[w][2] = v2; red[w][3] = v3;
    }
    __syncthreads();
    if (t == 0) {
        float s0 = red[0][0] + red[1][0] + red[2][0] + red[3][0];
        float s1 = red[0][1] + red[1][1] + red[2][1] + red[3][1];
        float s2 = red[0][2] + red[1][2] + red[2][2] + red[3][2];
        float s3 = red[0][3] + red[1][3] + red[2][3] + red[3][3];
        float hb = -hbc[0] * hbc[0];
        float hy = -hyc[0] * hyc[0];
        float inv = 1.f / (1.f + rtc[0] * rtc[0] * rotor[b]);
        out[b * 5 + 0] = s0 * inv;
        out[b * 5 + 1] = s1 * hb * inv;
        out[b * 5 + 2] = s2 * hb * inv;
        out[b * 5 + 3] = s3 * hy * inv;
        out[b * 5 + 4] = duff[b] * vdc[0] * vdc[0] * inv;
    }
}

// ---------------- host side ----------------
extern "C" void kernel_launch(void* const* d_in, const int* in_sizes, int n_in,
                              void* d_out, int out_size) {
    (void)in_sizes; (void)n_in; (void)out_size;
    const float* h1      = (const float*)d_in[0];
    const float* adj1    = (const float*)d_in[1];
    const float* h2      = (const float*)d_in[2];
    const float* adj2    = (const float*)d_in[3];
    const float* A_int   = (const float*)d_in[4];
    const float* pos1    = (const float*)d_in[5];
    const float* pos2    = (const float*)d_in[6];
    const float* rotor   = (const float*)d_in[7];
    const float* vdw_r1  = (const float*)d_in[8];
    const float* vdw_r2  = (const float*)d_in[9];
    const float* duff    = (const float*)d_in[10];
    const float* nm1     = (const float*)d_in[11];
    const float* nm2     = (const float*)d_in[12];
    const float* node_W  = (const float*)d_in[13];
    const float* gat_W   = (const float*)d_in[14];
    const float* gat_b   = (const float*)d_in[15];
    const float* gat_A   = (const float*)d_in[16];
    const float* gate_W  = (const float*)d_in[17];
    const float* gate_b  = (const float*)d_in[18];
    const float* vdwA_W1 = (const float*)d_in[19];
    const float* vdwA_b1 = (const float*)d_in[20];
    const float* vdwA_W2 = (const float*)d_in[21];
    const float* vdwA_b2 = (const float*)d_in[22];
    const float* vdwB_W1 = (const float*)d_in[23];
    const float* vdwB_b1 = (const float*)d_in[24];
    const float* vdwB_W2 = (const float*)d_in[25];
    const float* vdwB_b2 = (const float*)d_in[26];
    const float* hbond   = (const float*)d_in[27];
    const float* hydro   = (const float*)d_in[28];
    const float* vdwc    = (const float*)d_in[29];
    const float* rotc    = (const float*)d_in[30];
    float* out = (float*)d_out;

    float *gp, *hp_, *hAp, *e2p, *a2p, *e1p, *a1p, *wap, *bap;
    float *p1a, *p1b, *p2a, *p2b, *zap, *zbp, *partp;
    cudaGetSymbolAddress((void**)&gp,  g_g);
    cudaGetSymbolAddress((void**)&hp_, g_h);
    cudaGetSymbolAddress((void**)&hAp, g_hA);
    cudaGetSymbolAddress((void**)&e2p, g_e2);
    cudaGetSymbolAddress((void**)&a2p, g_a2);
    cudaGetSymbolAddress((void**)&e1p, g_e1);
    cudaGetSymbolAddress((void**)&a1p, g_a1);
    cudaGetSymbolAddress((void**)&wap, g_WA);
    cudaGetSymbolAddress((void**)&bap, g_bA);
    cudaGetSymbolAddress((void**)&p1a, g_P1A);
    cudaGetSymbolAddress((void**)&p1b, g_P1B);
    cudaGetSymbolAddress((void**)&p2a, g_P2A);
    cudaGetSymbolAddress((void**)&p2b, g_P2B);
    cudaGetSymbolAddress((void**)&zap, g_ZA);
    cudaGetSymbolAddress((void**)&zbp, g_ZB);
    cudaGetSymbolAddress((void**)&partp, g_part);

    (void)cudaFuncSetAttribute(k_softmax_both,
                               cudaFuncAttributeMaxDynamicSharedMemorySize,
                               NN2 * 33 * 4);

    // precompute WA, bA; embedding
    k_wa<<<dim3(2, 2, 3), 256>>>(gat_W, gat_A, wap);
    k_bvec<<<3, DD>>>(gat_b, gat_A, bap);
    k_embed_both<<<MROWS, DD>>>(h1, h2, node_W, gp);

    for (int l = 0; l < 3; l++) {
        const float* W  = gat_W  + (size_t)l * DD * DD;
        const float* bW = gat_b  + (size_t)l * DD;
        const float* WA = wap    + (size_t)l * DD * DD;
        const float* bA = bap    + (size_t)l * DD;
        const float* gW = gate_W + (size_t)l * 2 * DD;
        const float* gb = gate_b + l;
        k_dual<<<dim3(4, MROWS / 64, 1), 256>>>(gp, W, bW, WA, bA, hp_, hAp);
        k_nt_both<<<dim3(8, 8, 16), 256>>>(hp_, hAp, e2p, e1p);
        k_softmax_both<<<dim3(16, 16), dim3(32, 8), NN2 * 33 * 4>>>(e2p, adj2, a2p,
                                                                    e1p, adj1, a1p);
        k_relugate<<<dim3(1, 16, 16), 256>>>(a2p, a1p, hp_, gp, gW, gb);
    }

    // pair projections (one launch)
    k_proj<<<dim3(2, 64, 4), 256>>>(gp, vdwA_W1, vdwA_b1, vdwB_W1, vdwB_b1,
                                    p1a, p1b, p2a, p2b);
    // pair bilinear-relu MLP matrices
    k_zmat<<<dim3(16, 4, 16), 256>>>(p1a, p1b, p2a, p2b, vdwA_W2, vdwB_W2,
                                     vdwA_b2, vdwB_b2, zap, zbp);
    // physics + reductions
    k_phys<<<BB * NN1, 128>>>(zap, zbp, pos1, pos2, vdw_r1, vdw_r2, nm1, nm2,
                              A_int, partp);
    k_final<<<BB, 128>>>(partp, rotor, duff, hbond, hydro, vdwc, rotc, out);
}

// round 8
// speedup vs baseline: 1.3098x; 1.2640x over previous
#include <cuda_runtime.h>
#include <math.h>

#define BB  8
#define NN1 128
#define NN2 512
#define DD  128
#define MROWS (BB * (NN1 + NN2))   // 5120 combined rows
#define R1   (BB * NN1)            // 1024 graph-1 rows

// ---------------- static device scratch ----------------
__device__ float g_g  [MROWS * DD];
__device__ float g_h  [MROWS * DD];
__device__ float g_hA [MROWS * DD];
__device__ float g_hpart[4 * MROWS * DD];   // split-K partials for hp
__device__ float g_e2 [BB * NN2 * NN2];
__device__ float g_a2 [BB * NN2 * NN2];
__device__ float g_e1 [BB * NN1 * NN1];
__device__ float g_a1 [BB * NN1 * NN1];
__device__ float g_WA [3 * DD * DD];
__device__ float g_bA [3 * DD];
__device__ float g_P1A[BB * NN1 * DD];
__device__ float g_P1B[BB * NN1 * DD];
__device__ float g_P2A[BB * NN2 * DD];
__device__ float g_P2B[BB * NN2 * DD];
__device__ float g_ZA [BB * NN1 * NN2];
__device__ float g_ZB [BB * NN1 * NN2];
__device__ float g_part[BB * NN1 * 4];

// ---------------- packed f32x2 helpers (Blackwell FFMA2) ----------------
__device__ __forceinline__ unsigned long long pk2(float x, float y) {
    unsigned long long r;
    asm("mov.b64 %0, {%1, %2};" : "=l"(r) : "f"(x), "f"(y));
    return r;
}
__device__ __forceinline__ unsigned long long dup2(float x) {
    unsigned long long r;
    asm("mov.b64 %0, {%1, %1};" : "=l"(r) : "f"(x));
    return r;
}
__device__ __forceinline__ void fma2(unsigned long long& acc, unsigned long long a,
                                     unsigned long long b) {
    asm("fma.rn.f32x2 %0, %1, %2, %0;" : "+l"(acc) : "l"(a), "l"(b));
}
__device__ __forceinline__ float2 unpk(unsigned long long v) {
    float2 r;
    asm("mov.b64 {%0, %1}, %2;" : "=f"(r.x), "=f"(r.y) : "l"(v));
    return r;
}

// ---------------- generic 64x64 NN GEMM body with strides ----------------
__device__ __forceinline__ void gemm64k(const float* __restrict__ A, int lda,
                                        const float* __restrict__ B, int ldb,
                                        const float* __restrict__ bias,
                                        float* __restrict__ C, int ldc,
                                        int K, int m0, int n0) {
    __shared__ float As[16][68];
    __shared__ float Bs[16][68];
    int tid = threadIdx.x;
    int tx = tid & 15, ty = tid >> 4;
    int lm = tid >> 2, lkq = (tid & 3) * 4;
    int lk = tid >> 4, ln = (tid & 15) * 4;
    unsigned long long accp[4][2] = {};
    for (int k0 = 0; k0 < K; k0 += 16) {
        float4 a4 = *(const float4*)&A[(long)(m0 + lm) * lda + k0 + lkq];
        As[lkq + 0][lm] = a4.x; As[lkq + 1][lm] = a4.y;
        As[lkq + 2][lm] = a4.z; As[lkq + 3][lm] = a4.w;
        *(float4*)&Bs[lk][ln] = *(const float4*)&B[(long)(k0 + lk) * ldb + n0 + ln];
        __syncthreads();
        #pragma unroll
        for (int k = 0; k < 16; k++) {
            float4 av = *(float4*)&As[k][ty * 4];
            float4 bv = *(float4*)&Bs[k][tx * 4];
            unsigned long long b01 = pk2(bv.x, bv.y);
            unsigned long long b23 = pk2(bv.z, bv.w);
            float am[4] = {av.x, av.y, av.z, av.w};
            #pragma unroll
            for (int i = 0; i < 4; i++) {
                unsigned long long a2 = dup2(am[i]);
                fma2(accp[i][0], a2, b01);
                fma2(accp[i][1], a2, b23);
            }
        }
        __syncthreads();
    }
    #pragma unroll
    for (int i = 0; i < 4; i++) {
        int m = m0 + ty * 4 + i;
        int n = n0 + tx * 4;
        float2 c01 = unpk(accp[i][0]);
        float2 c23 = unpk(accp[i][1]);
        float4 v;
        v.x = c01.x + (bias ? bias[n + 0] : 0.f);
        v.y = c01.y + (bias ? bias[n + 1] : 0.f);
        v.z = c23.x + (bias ? bias[n + 2] : 0.f);
        v.w = c23.y + (bias ? bias[n + 3] : 0.f);
        *(float4*)&C[(long)m * ldc + n] = v;
    }
}

// WA[l] = gat_W[l] @ gat_A[l]
__global__ void k_wa(const float* __restrict__ W, const float* __restrict__ A,
                     float* __restrict__ WA) {
    int l = blockIdx.z;
    gemm64k(W + (long)l * DD * DD, DD, A + (long)l * DD * DD, DD, nullptr,
            WA + (long)l * DD * DD, DD, DD, blockIdx.y * 64, blockIdx.x * 64);
}

// bA[l] = gat_b[l] @ gat_A[l]
__global__ void k_bvec(const float* __restrict__ b, const float* __restrict__ A,
                       float* __restrict__ bA) {
    int l = blockIdx.x, n = threadIdx.x;
    float acc = 0.f;
    #pragma unroll 8
    for (int k = 0; k < DD; k++)
        acc += b[l * DD + k] * A[((long)l * DD + k) * DD + n];
    bA[l * DD + n] = acc;
}

// embedding for both graphs
__global__ void k_embed_both(const float* __restrict__ X1, const float* __restrict__ X2,
                             const float* __restrict__ W, float* __restrict__ Y) {
    int bn = blockIdx.x;
    const float* src = (bn < R1) ? X1 + (size_t)bn * 54
                                 : X2 + (size_t)(bn - R1) * 54;
    __shared__ float xs[54];
    if (threadIdx.x < 54) xs[threadIdx.x] = src[threadIdx.x];
    __syncthreads();
    int d = threadIdx.x;
    float acc = 0.f;
    #pragma unroll
    for (int l = 0; l < 54; l++) acc += xs[l] * W[l * DD + d];
    Y[(size_t)bn * DD + d] = acc;
}

// h = g@W + b ; hA = g@WA + bA  (one launch, 5120 rows)
__global__ void k_dual(const float* __restrict__ g, const float* __restrict__ W,
                       const float* __restrict__ b, const float* __restrict__ WA,
                       const float* __restrict__ bA, float* __restrict__ h,
                       float* __restrict__ hA) {
    int xi = blockIdx.x;
    const float* B; const float* bias; float* C; int n0;
    if (xi < 2) { B = W;  bias = b;  C = h;  n0 = xi * 64; }
    else        { B = WA; bias = bA; C = hA; n0 = (xi - 2) * 64; }
    gemm64k(g, DD, B, DD, bias, C, DD, DD, blockIdx.y * 64, n0);
}

// e = hA @ h^T, both graphs (z<8: graph2 N=512; z>=8: graph1 N=128)
__global__ void k_nt_both(const float* __restrict__ h, const float* __restrict__ hA,
                          float* __restrict__ e2, float* __restrict__ e1) {
    int z = blockIdx.z;
    int N; const float* Ab; const float* Bb; float* Cb;
    if (z < 8) {
        N = NN2;
        Ab = hA + ((long)R1 + (long)z * NN2) * DD;
        Bb = h  + ((long)R1 + (long)z * NN2) * DD;
        Cb = e2 + (long)z * NN2 * NN2;
    } else {
        if (blockIdx.x >= 2 || blockIdx.y >= 2) return;
        N = NN1;
        Ab = hA + (long)(z - 8) * NN1 * DD;
        Bb = h  + (long)(z - 8) * NN1 * DD;
        Cb = e1 + (long)(z - 8) * NN1 * NN1;
    }
    __shared__ float As[16][68];
    __shared__ float Bs[16][68];
    int m0 = blockIdx.y * 64, n0 = blockIdx.x * 64;
    int tid = threadIdx.x;
    int tx = tid & 15, ty = tid >> 4;
    int lm = tid >> 2, lkq = (tid & 3) * 4;
    unsigned long long accp[4][2] = {};
    for (int k0 = 0; k0 < DD; k0 += 16) {
        float4 a4 = *(const float4*)&Ab[(long)(m0 + lm) * DD + k0 + lkq];
        As[lkq + 0][lm] = a4.x; As[lkq + 1][lm] = a4.y;
        As[lkq + 2][lm] = a4.z; As[lkq + 3][lm] = a4.w;
        float4 b4 = *(const float4*)&Bb[(long)(n0 + lm) * DD + k0 + lkq];
        Bs[lkq + 0][lm] = b4.x; Bs[lkq + 1][lm] = b4.y;
        Bs[lkq + 2][lm] = b4.z; Bs[lkq + 3][lm] = b4.w;
        __syncthreads();
        #pragma unroll
        for (int k = 0; k < 16; k++) {
            float4 av = *(float4*)&As[k][ty * 4];
            float4 bv = *(float4*)&Bs[k][tx * 4];
            unsigned long long b01 = pk2(bv.x, bv.y);
            unsigned long long b23 = pk2(bv.z, bv.w);
            float am[4] = {av.x, av.y, av.z, av.w};
            #pragma unroll
            for (int i = 0; i < 4; i++) {
                unsigned long long a2 = dup2(am[i]);
                fma2(accp[i][0], a2, b01);
                fma2(accp[i][1], a2, b23);
            }
        }
        __syncthreads();
    }
    #pragma unroll
    for (int i = 0; i < 4; i++) {
        int m = m0 + ty * 4 + i, n = n0 + tx * 4;
        float2 c01 = unpk(accp[i][0]);
        float2 c23 = unpk(accp[i][1]);
        float4 v = {c01.x, c01.y, c23.x, c23.y};
        *(float4*)&Cb[(long)m * N + n] = v;
    }
}

// fused symmetrize + mask + column softmax (axis=1), both graphs
__global__ void k_softmax_both(const float* __restrict__ e2, const float* __restrict__ adj2,
                               float* __restrict__ a2, const float* __restrict__ e1,
                               const float* __restrict__ adj1, float* __restrict__ a1) {
    extern __shared__ float Ls[];   // N*33 floats
    __shared__ float Ts[32][33];
    __shared__ float red[8][33];
    int z = blockIdx.y;
    int N; const float* Eb; const float* Ab; float* Ob;
    if (z < 8) {
        N = NN2;
        Eb = e2 + (long)z * NN2 * NN2; Ab = adj2 + (long)z * NN2 * NN2;
        Ob = a2 + (long)z * NN2 * NN2;
    } else {
        if (blockIdx.x >= NN1 / 32) return;
        N = NN1;
        Eb = e1 + (long)(z - 8) * NN1 * NN1; Ab = adj1 + (long)(z - 8) * NN1 * NN1;
        Ob = a1 + (long)(z - 8) * NN1 * NN1;
    }
    int k0 = blockIdx.x * 32;
    int tx = threadIdx.x, ty = threadIdx.y;
    for (int i0 = 0; i0 < N; i0 += 32) {
        for (int r = ty; r < 32; r += 8)
            Ts[r][tx] = Eb[(size_t)(k0 + r) * N + i0 + tx];
        __syncthreads();
        for (int r = ty; r < 32; r += 8) {
            float d = Eb[(size_t)(i0 + r) * N + k0 + tx];
            float a = Ab[(size_t)(i0 + r) * N + k0 + tx];
            Ls[(i0 + r) * 33 + tx] = (a > 0.f) ? (d + Ts[tx][r]) : -9e15f;
        }
        __syncthreads();
    }
    float m = -3.4e38f;
    for (int i = ty; i < N; i += 8) m = fmaxf(m, Ls[i * 33 + tx]);
    red[ty][tx] = m;
    __syncthreads();
    if (ty == 0) {
        float mm = red[0][tx];
        #pragma unroll
        for (int y = 1; y < 8; y++) mm = fmaxf(mm, red[y][tx]);
        red[0][tx] = mm;
    }
    __syncthreads();
    m = red[0][tx];
    __syncthreads();
    float s = 0.f;
    for (int i = ty; i < N; i += 8) {
        float e = __expf(Ls[i * 33 + tx] - m);
        Ls[i * 33 + tx] = e;
        s += e;
    }
    red[ty][tx] = s;
    __syncthreads();
    if (ty == 0) {
        float ss = 0.f;
        #pragma unroll
        for (int y = 0; y < 8; y++) ss += red[y][tx];
        red[0][tx] = ss;
    }
    __syncthreads();
    float inv = 1.f / red[0][tx];
    for (int i = ty; i < N; i += 8)
        Ob[(size_t)i * N + k0 + tx] = Ls[i * 33 + tx] * inv;
}

// split-K hp GEMM: part[chunk] = att(chunk cols) @ h(chunk rows)
// z<8 graph2 (K=512 in 4 chunks of 128), z>=8 graph1 (K=128, 1 chunk)
__global__ void k_hp(const float* __restrict__ a2, const float* __restrict__ a1,
                     const float* __restrict__ h, float* __restrict__ part) {
    int z = blockIdx.z;
    if (z < 8) {
        int chunk = blockIdx.x >> 1, nt = blockIdx.x & 1;
        const float* A = a2 + (long)z * NN2 * NN2 + chunk * 128;
        const float* B = h + ((long)R1 + (long)z * NN2 + chunk * 128) * DD;
        float* C = part + (long)chunk * MROWS * DD + ((long)R1 + (long)z * NN2) * DD;
        gemm64k(A, NN2, B, DD, nullptr, C, DD, 128, blockIdx.y * 64, nt * 64);
    } else {
        if (blockIdx.x >= 2 || blockIdx.y >= 2) return;
        const float* A = a1 + (long)(z - 8) * NN1 * NN1;
        const float* B = h + (long)(z - 8) * NN1 * DD;
        float* C = part + (long)(z - 8) * NN1 * DD;
        gemm64k(A, NN1, B, DD, nullptr, C, DD, NN1, blockIdx.y * 64, blockIdx.x * 64);
    }
}

// gate: hp = relu(sum chunks); c = sigmoid(g.gW1 + hp.gW2 + gb); g = c*g + (1-c)*hp
__global__ void k_gate(float* __restrict__ g, const float* __restrict__ part,
                       const float* __restrict__ gW, const float* __restrict__ gb) {
    long row = blockIdx.x;
    int t = threadIdx.x;
    float hp = part[row * DD + t];
    if (row >= R1) {
        hp += part[(long)1 * MROWS * DD + row * DD + t];
        hp += part[(long)2 * MROWS * DD + row * DD + t];
        hp += part[(long)3 * MROWS * DD + row * DD + t];
    }
    hp = fmaxf(hp, 0.f);
    float x = g[row * DD + t];
    float v = x * gW[t] + hp * gW[DD + t];
    #pragma unroll
    for (int o = 16; o > 0; o >>= 1) v += __shfl_down_sync(0xffffffffu, v, o);
    __shared__ float red[4];
    __shared__ float csh;
    if ((t & 31) == 0) red[t >> 5] = v;
    __syncthreads();
    if (t == 0) {
        float s = red[0] + red[1] + red[2] + red[3] + gb[0];
        csh = 1.f / (1.f + __expf(-s));
    }
    __syncthreads();
    float c = csh;
    g[row * DD + t] = c * x + (1.f - c) * hp;
}

// all 4 pair projections in one launch (z: 0=p1a 1=p1b 2=p2a 3=p2b)
__global__ void k_proj(const float* __restrict__ g,
                       const float* __restrict__ WA1, const float* __restrict__ bA1,
                       const float* __restrict__ WB1, const float* __restrict__ bB1,
                       float* __restrict__ p1a, float* __restrict__ p1b,
                       float* __restrict__ p2a, float* __restrict__ p2b) {
    int z = blockIdx.z;
    const float* A; const float* B; const float* bias; float* C; int mt;
    switch (z) {
        case 0: A = g;            B = WA1;           bias = bA1;   C = p1a; mt = R1 / 64; break;
        case 1: A = g;            B = WB1;           bias = bB1;   C = p1b; mt = R1 / 64; break;
        case 2: A = g + (long)R1 * DD; B = WA1 + DD * DD; bias = nullptr; C = p2a; mt = (BB * NN2) / 64; break;
        default:A = g + (long)R1 * DD; B = WB1 + DD * DD; bias = nullptr; C = p2b; mt = (BB * NN2) / 64; break;
    }
    if ((int)blockIdx.y >= mt) return;
    gemm64k(A, DD, B, DD, bias, C, DD, DD, blockIdx.y * 64, blockIdx.x * 64);
}

// Z[b,i,j] = act( b2 + sum_h relu(P1[i,h]+P2[j,h]) * w2[h] ), 32x32 tiles
__global__ void k_zmat(const float* __restrict__ p1a, const float* __restrict__ p1b,
                       const float* __restrict__ p2a, const float* __restrict__ p2b,
                       const float* __restrict__ w2A, const float* __restrict__ w2B,
                       const float* __restrict__ b2A, const float* __restrict__ b2B,
                       float* __restrict__ ZA, float* __restrict__ ZB) {
    __shared__ float P1s[DD][33];
    __shared__ float P2s[DD][33];
    __shared__ float w2s[DD];
    int z = blockIdx.z;
    int b = z >> 1, mlp = z & 1;
    const float* P1 = (mlp ? p1b : p1a) + (long)b * NN1 * DD;
    const float* P2 = (mlp ? p2b : p2a) + (long)b * NN2 * DD;
    const float* w2 = mlp ? w2B : w2A;
    float b2 = mlp ? b2B[0] : b2A[0];
    float* Z = (mlp ? ZB : ZA) + (long)b * NN1 * NN2;
    int i0 = blockIdx.y * 32, j0 = blockIdx.x * 32;
    int tid = threadIdx.x;
    if (tid < DD) w2s[tid] = w2[tid];
    {
        int row = tid >> 3, cb = (tid & 7) * 16;
        #pragma unroll
        for (int q = 0; q < 4; q++) {
            float4 v1 = *(const float4*)&P1[(long)(i0 + row) * DD + cb + q * 4];
            float4 v2 = *(const float4*)&P2[(long)(j0 + row) * DD + cb + q * 4];
            P1s[cb + q * 4 + 0][row] = v1.x; P1s[cb + q * 4 + 1][row] = v1.y;
            P1s[cb + q * 4 + 2][row] = v1.z; P1s[cb + q * 4 + 3][row] = v1.w;
            P2s[cb + q * 4 + 0][row] = v2.x; P2s[cb + q * 4 + 1][row] = v2.y;
            P2s[cb + q * 4 + 2][row] = v2.z; P2s[cb + q * 4 + 3][row] = v2.w;
        }
    }
    __syncthreads();
    int tx = tid & 15, ty = tid >> 4;
    float a00 = 0.f, a01 = 0.f, a10 = 0.f, a11 = 0.f;
    #pragma unroll 4
    for (int k = 0; k < DD; k++) {
        float w = w2s[k];
        float p0 = P1s[k][ty], p1 = P1s[k][ty + 16];
        float q0 = P2s[k][tx], q1 = P2s[k][tx + 16];
        a00 += fmaxf(p0 + q0, 0.f) * w;
        a01 += fmaxf(p0 + q1, 0.f) * w;
        a10 += fmaxf(p1 + q0, 0.f) * w;
        a11 += fmaxf(p1 + q1, 0.f) * w;
    }
    a00 += b2; a01 += b2; a10 += b2; a11 += b2;
    if (mlp == 0) {
        a00 = 1.f / (1.f + __expf(-a00)); a01 = 1.f / (1.f + __expf(-a01));
        a10 = 1.f / (1.f + __expf(-a10)); a11 = 1.f / (1.f + __expf(-a11));
    } else {
        a00 = tanhf(a00) * 0.2f; a01 = tanhf(a01) * 0.2f;
        a10 = tanhf(a10) * 0.2f; a11 = tanhf(a11) * 0.2f;
    }
    Z[(long)(i0 + ty) * NN2 + j0 + tx]           = a00;
    Z[(long)(i0 + ty) * NN2 + j0 + tx + 16]      = a01;
    Z[(long)(i0 + ty + 16) * NN2 + j0 + tx]      = a10;
    Z[(long)(i0 + ty + 16) * NN2 + j0 + tx + 16] = a11;
}

// elementwise physics + per-(b,i) reduction
__global__ void k_phys(const float* __restrict__ ZA, const float* __restrict__ ZB,
                       const float* __restrict__ pos1, const float* __restrict__ pos2,
                       const float* __restrict__ r1, const float* __restrict__ r2,
                       const float* __restrict__ nm1, const float* __restrict__ nm2,
                       const float* __restrict__ A_int, float* __restrict__ part) {
    int b = blockIdx.x >> 7, i = blockIdx.x & 127;
    int t = threadIdx.x;
    float px = pos1[(b * NN1 + i) * 3 + 0];
    float py = pos1[(b * NN1 + i) * 3 + 1];
    float pz = pos1[(b * NN1 + i) * 3 + 2];
    float rr1 = r1[b * NN1 + i];
    float m1  = nm1[b * NN1 + i];
    size_t zbase = (size_t)b * NN1 * NN2 + (size_t)i * NN2;
    size_t abase = (size_t)b * 8 * NN1 * NN2 + (size_t)i * NN2;
    const size_t chw = (size_t)NN1 * NN2;
    float s0 = 0.f, s1 = 0.f, s2 = 0.f, s3 = 0.f;
    for (int j = t; j < NN2; j += 128) {
        float Aw = ZA[zbase + j];
        float Bw = ZB[zbase + j];
        float dx = px - pos2[(b * NN2 + j) * 3 + 0];
        float dy = py - pos2[(b * NN2 + j) * 3 + 1];
        float dz = pz - pos2[(b * NN2 + j) * 3 + 2];
        float dm = sqrtf(dx * dx + dy * dy + dz * dz + 1e-10f);
        if (dm < 0.5f) dm = 1e10f;
        float dm0 = rr1 + r2[b * NN2 + j] + Bw;
        float dm0s = (dm0 < 1e-4f) ? 1.f : dm0;
        float rq = dm0s / dm;
        float rq2 = rq * rq;
        float r6 = rq2 * rq2 * rq2;
        float evdw = fminf(r6 * r6 - 2.f * r6, 100.f);
        float Aamp = Aw * (0.0356f - 0.0178f) + 0.0178f;
        s0 += Aamp * evdw * m1 * nm2[b * NN2 + j];
        float dmd = dm - dm0;
        float a1 = A_int[abase + 1 * chw + j];
        float a7 = A_int[abase + 7 * chw + j];
        float a6 = A_int[abase + 6 * chw + j];
        s1 += fminf(fmaxf(dmd * a1 * (-1.f / 0.7f), 0.f), 1.f);
        s2 += fminf(fmaxf(dmd * a7 * (-1.f / 0.7f), 0.f), 1.f);
        s3 += fminf(fmaxf((1.5f - dmd) * a6, 0.f), 1.f);
    }
    #pragma unroll
    for (int o = 16; o > 0; o >>= 1) {
        s0 += __shfl_down_sync(0xffffffffu, s0, o);
        s1 += __shfl_down_sync(0xffffffffu, s1, o);
        s2 += __shfl_down_sync(0xffffffffu, s2, o);
        s3 += __shfl_down_sync(0xffffffffu, s3, o);
    }
    __shared__ float acc[4][4];
    int lane = t & 31, w = t >> 5;
    if (lane == 0) { acc[w][0] = s0; acc[w][1] = s1; acc[w][2] = s2; acc[w][3] = s3; }
    __syncthreads();
    if (t < 4)
        part[((size_t)b * NN1 + i) * 4 + t] = acc[0][t] + acc[1][t] + acc[2][t] + acc[3][t];
}

__global__ void k_final(const float* __restrict__ part, const float* __restrict__ rotor,
                        const float* __restrict__ duff, const float* __restrict__ hbc,
                        const float* __restrict__ hyc, const float* __restrict__ vdc,
                        const float* __restrict__ rtc, float* __restrict__ out) {
    int b = blockIdx.x, t = threadIdx.x;
    size_t base = ((size_t)b * NN1 + t) * 4;
    float v0 = part[base + 0], v1 = part[base + 1], v2 = part[base + 2], v3 = part[base + 3];
    #pragma unroll
    for (int o = 16; o > 0; o >>= 1) {
        v0 += __shfl_down_sync(0xffffffffu, v0, o);
        v1 += __shfl_down_sync(0xffffffffu, v1, o);
        v2 += __shfl_down_sync(0xffffffffu, v2, o);
        v3 += __shfl_down_sync(0xffffffffu, v3, o);
    }
    __shared__ float red[4][4];
    if ((t & 31) == 0) {
        int w = t >> 5;
        red[w][0] = v0; red[w][1] = v1; red[w][2] = v2; red[w][3] = v3;
    }
    __syncthreads();
    if (t == 0) {
        float s0 = red[0][0] + red[1][0] + red[2][0] + red[3][0];
        float s1 = red[0][1] + red[1][1] + red[2][1] + red[3][1];
        float s2 = red[0][2] + red[1][2] + red[2][2] + red[3][2];
        float s3 = red[0][3] + red[1][3] + red[2][3] + red[3][3];
        float hb = -hbc[0] * hbc[0];
        float hy = -hyc[0] * hyc[0];
        float inv = 1.f / (1.f + rtc[0] * rtc[0] * rotor[b]);
        out[b * 5 + 0] = s0 * inv;
        out[b * 5 + 1] = s1 * hb * inv;
        out[b * 5 + 2] = s2 * hb * inv;
        out[b * 5 + 3] = s3 * hy * inv;
        out[b * 5 + 4] = duff[b] * vdc[0] * vdc[0] * inv;
    }
}

// ---------------- host side ----------------
extern "C" void kernel_launch(void* const* d_in, const int* in_sizes, int n_in,
                              void* d_out, int out_size) {
    (void)in_sizes; (void)n_in; (void)out_size;
    const float* h1      = (const float*)d_in[0];
    const float* adj1    = (const float*)d_in[1];
    const float* h2      = (const float*)d_in[2];
    const float* adj2    = (const float*)d_in[3];
    const float* A_int   = (const float*)d_in[4];
    const float* pos1    = (const float*)d_in[5];
    const float* pos2    = (const float*)d_in[6];
    const float* rotor   = (const float*)d_in[7];
    const float* vdw_r1  = (const float*)d_in[8];
    const float* vdw_r2  = (const float*)d_in[9];
    const float* duff    = (const float*)d_in[10];
    const float* nm1     = (const float*)d_in[11];
    const float* nm2     = (const float*)d_in[12];
    const float* node_W  = (const float*)d_in[13];
    const float* gat_W   = (const float*)d_in[14];
    const float* gat_b   = (const float*)d_in[15];
    const float* gat_A   = (const float*)d_in[16];
    const float* gate_W  = (const float*)d_in[17];
    const float* gate_b  = (const float*)d_in[18];
    const float* vdwA_W1 = (const float*)d_in[19];
    const float* vdwA_b1 = (const float*)d_in[20];
    const float* vdwA_W2 = (const float*)d_in[21];
    const float* vdwA_b2 = (const float*)d_in[22];
    const float* vdwB_W1 = (const float*)d_in[23];
    const float* vdwB_b1 = (const float*)d_in[24];
    const float* vdwB_W2 = (const float*)d_in[25];
    const float* vdwB_b2 = (const float*)d_in[26];
    const float* hbond   = (const float*)d_in[27];
    const float* hydro   = (const float*)d_in[28];
    const float* vdwc    = (const float*)d_in[29];
    const float* rotc    = (const float*)d_in[30];
    float* out = (float*)d_out;

    float *gp, *hp_, *hAp, *hpart, *e2p, *a2p, *e1p, *a1p, *wap, *bap;
    float *p1a, *p1b, *p2a, *p2b, *zap, *zbp, *partp;
    cudaGetSymbolAddress((void**)&gp,  g_g);
    cudaGetSymbolAddress((void**)&hp_, g_h);
    cudaGetSymbolAddress((void**)&hAp, g_hA);
    cudaGetSymbolAddress((void**)&hpart, g_hpart);
    cudaGetSymbolAddress((void**)&e2p, g_e2);
    cudaGetSymbolAddress((void**)&a2p, g_a2);
    cudaGetSymbolAddress((void**)&e1p, g_e1);
    cudaGetSymbolAddress((void**)&a1p, g_a1);
    cudaGetSymbolAddress((void**)&wap, g_WA);
    cudaGetSymbolAddress((void**)&bap, g_bA);
    cudaGetSymbolAddress((void**)&p1a, g_P1A);
    cudaGetSymbolAddress((void**)&p1b, g_P1B);
    cudaGetSymbolAddress((void**)&p2a, g_P2A);
    cudaGetSymbolAddress((void**)&p2b, g_P2B);
    cudaGetSymbolAddress((void**)&zap, g_ZA);
    cudaGetSymbolAddress((void**)&zbp, g_ZB);
    cudaGetSymbolAddress((void**)&partp, g_part);

    (void)cudaFuncSetAttribute(k_softmax_both,
                               cudaFuncAttributeMaxDynamicSharedMemorySize,
                               NN2 * 33 * 4);

    // precompute WA, bA; embedding
    k_wa<<<dim3(2, 2, 3), 256>>>(gat_W, gat_A, wap);
    k_bvec<<<3, DD>>>(gat_b, gat_A, bap);
    k_embed_both<<<MROWS, DD>>>(h1, h2, node_W, gp);

    for (int l = 0; l < 3; l++) {
        const float* W  = gat_W  + (size_t)l * DD * DD;
        const float* bW = gat_b  + (size_t)l * DD;
        const float* WA = wap    + (size_t)l * DD * DD;
        const float* bA = bap    + (size_t)l * DD;
        const float* gW = gate_W + (size_t)l * 2 * DD;
        const float* gb = gate_b + l;
        k_dual<<<dim3(4, MROWS / 64, 1), 256>>>(gp, W, bW, WA, bA, hp_, hAp);
        k_nt_both<<<dim3(8, 8, 16), 256>>>(hp_, hAp, e2p, e1p);
        k_softmax_both<<<dim3(16, 16), dim3(32, 8), NN2 * 33 * 4>>>(e2p, adj2, a2p,
                                                                    e1p, adj1, a1p);
        k_hp<<<dim3(8, 8, 16), 256>>>(a2p, a1p, hp_, hpart);
        k_gate<<<MROWS, DD>>>(gp, hpart, gW, gb);
    }

    // pair projections (one launch)
    k_proj<<<dim3(2, 64, 4), 256>>>(gp, vdwA_W1, vdwA_b1, vdwB_W1, vdwB_b1,
                                    p1a, p1b, p2a, p2b);
    // pair bilinear-relu MLP matrices
    k_zmat<<<dim3(16, 4, 16), 256>>>(p1a, p1b, p2a, p2b, vdwA_W2, vdwB_W2,
                                     vdwA_b2, vdwB_b2, zap, zbp);
    // physics + reductions
    k_phys<<<BB * NN1, 128>>>(zap, zbp, pos1, pos2, vdw_r1, vdw_r2, nm1, nm2,
                              A_int, partp);
    k_final<<<BB, 128>>>(partp, rotor, duff, hbond, hydro, vdwc, rotc, out);
}

// round 9
// speedup vs baseline: 1.7107x; 1.3061x over previous
#include <cuda_runtime.h>
#include <math.h>

#define BB  8
#define NN1 128
#define NN2 512
#define DD  128
#define MROWS (BB * (NN1 + NN2))   // 5120 combined rows
#define R1   (BB * NN1)            // 1024 graph-1 rows

// ---------------- static device scratch ----------------
__device__ float g_g  [MROWS * DD];
__device__ float g_h  [MROWS * DD];
__device__ float g_hA [MROWS * DD];
__device__ float g_hpart[4 * MROWS * DD];   // split-K partials for hp
__device__ float g_e2 [BB * NN2 * NN2];     // masked symmetric logits (graph2)
__device__ float g_a2 [BB * NN2 * NN2];     // row-softmax R (graph2)
__device__ float g_e1 [BB * NN1 * NN1];
__device__ float g_a1 [BB * NN1 * NN1];
__device__ float g_WA [3 * DD * DD];
__device__ float g_bA [3 * DD];
__device__ float g_P1A[BB * NN1 * DD];
__device__ float g_P1B[BB * NN1 * DD];
__device__ float g_P2A[BB * NN2 * DD];
__device__ float g_P2B[BB * NN2 * DD];
__device__ float g_ZA [BB * NN1 * NN2];
__device__ float g_ZB [BB * NN1 * NN2];
__device__ float g_part[BB * NN1 * 4];

// ---------------- packed f32x2 helpers (Blackwell FFMA2) ----------------
__device__ __forceinline__ unsigned long long pk2(float x, float y) {
    unsigned long long r;
    asm("mov.b64 %0, {%1, %2};" : "=l"(r) : "f"(x), "f"(y));
    return r;
}
__device__ __forceinline__ unsigned long long dup2(float x) {
    unsigned long long r;
    asm("mov.b64 %0, {%1, %1};" : "=l"(r) : "f"(x));
    return r;
}
__device__ __forceinline__ void fma2(unsigned long long& acc, unsigned long long a,
                                     unsigned long long b) {
    asm("fma.rn.f32x2 %0, %1, %2, %0;" : "+l"(acc) : "l"(a), "l"(b));
}
__device__ __forceinline__ float2 unpk(unsigned long long v) {
    float2 r;
    asm("mov.b64 {%0, %1}, %2;" : "=f"(r.x), "=f"(r.y) : "l"(v));
    return r;
}

// ---------------- generic 64x64 NN GEMM body with strides ----------------
__device__ __forceinline__ void gemm64k(const float* __restrict__ A, int lda,
                                        const float* __restrict__ B, int ldb,
                                        const float* __restrict__ bias,
                                        float* __restrict__ C, int ldc,
                                        int K, int m0, int n0) {
    __shared__ float As[16][68];
    __shared__ float Bs[16][68];
    int tid = threadIdx.x;
    int tx = tid & 15, ty = tid >> 4;
    int lm = tid >> 2, lkq = (tid & 3) * 4;
    int lk = tid >> 4, ln = (tid & 15) * 4;
    unsigned long long accp[4][2] = {};
    for (int k0 = 0; k0 < K; k0 += 16) {
        float4 a4 = *(const float4*)&A[(long)(m0 + lm) * lda + k0 + lkq];
        As[lkq + 0][lm] = a4.x; As[lkq + 1][lm] = a4.y;
        As[lkq + 2][lm] = a4.z; As[lkq + 3][lm] = a4.w;
        *(float4*)&Bs[lk][ln] = *(const float4*)&B[(long)(k0 + lk) * ldb + n0 + ln];
        __syncthreads();
        #pragma unroll
        for (int k = 0; k < 16; k++) {
            float4 av = *(float4*)&As[k][ty * 4];
            float4 bv = *(float4*)&Bs[k][tx * 4];
            unsigned long long b01 = pk2(bv.x, bv.y);
            unsigned long long b23 = pk2(bv.z, bv.w);
            float am[4] = {av.x, av.y, av.z, av.w};
            #pragma unroll
            for (int i = 0; i < 4; i++) {
                unsigned long long a2 = dup2(am[i]);
                fma2(accp[i][0], a2, b01);
                fma2(accp[i][1], a2, b23);
            }
        }
        __syncthreads();
    }
    #pragma unroll
    for (int i = 0; i < 4; i++) {
        int m = m0 + ty * 4 + i;
        int n = n0 + tx * 4;
        float2 c01 = unpk(accp[i][0]);
        float2 c23 = unpk(accp[i][1]);
        float4 v;
        v.x = c01.x + (bias ? bias[n + 0] : 0.f);
        v.y = c01.y + (bias ? bias[n + 1] : 0.f);
        v.z = c23.x + (bias ? bias[n + 2] : 0.f);
        v.w = c23.y + (bias ? bias[n + 3] : 0.f);
        *(float4*)&C[(long)m * ldc + n] = v;
    }
}

// ---------------- 64x64 TN GEMM body: C[m,n] = sum_k A[k, m0+m] * B[k, n0+n] ----------------
__device__ __forceinline__ void gemm64tn(const float* __restrict__ A, int lda,
                                         const float* __restrict__ B, int ldb,
                                         float* __restrict__ C, int ldc,
                                         int K, int m0, int n0) {
    __shared__ float As[16][68];
    __shared__ float Bs[16][68];
    int tid = threadIdx.x;
    int tx = tid & 15, ty = tid >> 4;
    int lk = tid >> 4, lq = (tid & 15) * 4;
    unsigned long long accp[4][2] = {};
    for (int k0 = 0; k0 < K; k0 += 16) {
        *(float4*)&As[lk][lq] = *(const float4*)&A[(long)(k0 + lk) * lda + m0 + lq];
        *(float4*)&Bs[lk][lq] = *(const float4*)&B[(long)(k0 + lk) * ldb + n0 + lq];
        __syncthreads();
        #pragma unroll
        for (int k = 0; k < 16; k++) {
            float4 av = *(float4*)&As[k][ty * 4];
            float4 bv = *(float4*)&Bs[k][tx * 4];
            unsigned long long b01 = pk2(bv.x, bv.y);
            unsigned long long b23 = pk2(bv.z, bv.w);
            float am[4] = {av.x, av.y, av.z, av.w};
            #pragma unroll
            for (int i = 0; i < 4; i++) {
                unsigned long long a2 = dup2(am[i]);
                fma2(accp[i][0], a2, b01);
                fma2(accp[i][1], a2, b23);
            }
        }
        __syncthreads();
    }
    #pragma unroll
    for (int i = 0; i < 4; i++) {
        int m = m0 + ty * 4 + i, n = n0 + tx * 4;
        float2 c01 = unpk(accp[i][0]);
        float2 c23 = unpk(accp[i][1]);
        float4 v = {c01.x, c01.y, c23.x, c23.y};
        *(float4*)&C[(long)m * ldc + n] = v;
    }
}

// WA[l] = gat_W[l] @ gat_A[l]
__global__ void k_wa(const float* __restrict__ W, const float* __restrict__ A,
                     float* __restrict__ WA) {
    int l = blockIdx.z;
    gemm64k(W + (long)l * DD * DD, DD, A + (long)l * DD * DD, DD, nullptr,
            WA + (long)l * DD * DD, DD, DD, blockIdx.y * 64, blockIdx.x * 64);
}

// bA[l] = gat_b[l] @ gat_A[l]
__global__ void k_bvec(const float* __restrict__ b, const float* __restrict__ A,
                       float* __restrict__ bA) {
    int l = blockIdx.x, n = threadIdx.x;
    float acc = 0.f;
    #pragma unroll 8
    for (int k = 0; k < DD; k++)
        acc += b[l * DD + k] * A[((long)l * DD + k) * DD + n];
    bA[l * DD + n] = acc;
}

// embedding for both graphs
__global__ void k_embed_both(const float* __restrict__ X1, const float* __restrict__ X2,
                             const float* __restrict__ W, float* __restrict__ Y) {
    int bn = blockIdx.x;
    const float* src = (bn < R1) ? X1 + (size_t)bn * 54
                                 : X2 + (size_t)(bn - R1) * 54;
    __shared__ float xs[54];
    if (threadIdx.x < 54) xs[threadIdx.x] = src[threadIdx.x];
    __syncthreads();
    int d = threadIdx.x;
    float acc = 0.f;
    #pragma unroll
    for (int l = 0; l < 54; l++) acc += xs[l] * W[l * DD + d];
    Y[(size_t)bn * DD + d] = acc;
}

// h = g@W + b ; hA = g@WA + bA  (one launch, 5120 rows)
__global__ void k_dual(const float* __restrict__ g, const float* __restrict__ W,
                       const float* __restrict__ b, const float* __restrict__ WA,
                       const float* __restrict__ bA, float* __restrict__ h,
                       float* __restrict__ hA) {
    int xi = blockIdx.x;
    const float* B; const float* bias; float* C; int n0;
    if (xi < 2) { B = W;  bias = b;  C = h;  n0 = xi * 64; }
    else        { B = WA; bias = bA; C = hA; n0 = (xi - 2) * 64; }
    gemm64k(g, DD, B, DD, bias, C, DD, DD, blockIdx.y * 64, n0);
}

// masked symmetric logits: L[m,n] = adj>0 ? (hA_m.h_n + h_m.hA_n) : -9e15
// (e + e^T fused into the GEMM; L is symmetric -> row softmax == column softmax^T)
__global__ void k_ntsym(const float* __restrict__ h, const float* __restrict__ hA,
                        const float* __restrict__ adj2, float* __restrict__ e2,
                        const float* __restrict__ adj1, float* __restrict__ e1) {
    int z = blockIdx.z;
    int N; const float* Hb; const float* Ab; const float* Adj; float* Cb;
    if (z < 8) {
        N = NN2;
        Hb = h  + ((long)R1 + (long)z * NN2) * DD;
        Ab = hA + ((long)R1 + (long)z * NN2) * DD;
        Adj = adj2 + (long)z * NN2 * NN2;
        Cb = e2 + (long)z * NN2 * NN2;
    } else {
        if (blockIdx.x >= 2 || blockIdx.y >= 2) return;
        N = NN1;
        Hb = h  + (long)(z - 8) * NN1 * DD;
        Ab = hA + (long)(z - 8) * NN1 * DD;
        Adj = adj1 + (long)(z - 8) * NN1 * NN1;
        Cb = e1 + (long)(z - 8) * NN1 * NN1;
    }
    __shared__ float AsA[16][68];   // hA rows m (as [k][m])
    __shared__ float AsH[16][68];   // h  rows m
    __shared__ float BsH[16][68];   // h  rows n
    __shared__ float BsA[16][68];   // hA rows n
    int m0 = blockIdx.y * 64, n0 = blockIdx.x * 64;
    int tid = threadIdx.x;
    int tx = tid & 15, ty = tid >> 4;
    int lm = tid >> 2, lkq = (tid & 3) * 4;
    unsigned long long accp[4][2] = {};
    for (int k0 = 0; k0 < DD; k0 += 16) {
        float4 aA = *(const float4*)&Ab[(long)(m0 + lm) * DD + k0 + lkq];
        AsA[lkq + 0][lm] = aA.x; AsA[lkq + 1][lm] = aA.y;
        AsA[lkq + 2][lm] = aA.z; AsA[lkq + 3][lm] = aA.w;
        float4 aH = *(const float4*)&Hb[(long)(m0 + lm) * DD + k0 + lkq];
        AsH[lkq + 0][lm] = aH.x; AsH[lkq + 1][lm] = aH.y;
        AsH[lkq + 2][lm] = aH.z; AsH[lkq + 3][lm] = aH.w;
        float4 bH = *(const float4*)&Hb[(long)(n0 + lm) * DD + k0 + lkq];
        BsH[lkq + 0][lm] = bH.x; BsH[lkq + 1][lm] = bH.y;
        BsH[lkq + 2][lm] = bH.z; BsH[lkq + 3][lm] = bH.w;
        float4 bA4 = *(const float4*)&Ab[(long)(n0 + lm) * DD + k0 + lkq];
        BsA[lkq + 0][lm] = bA4.x; BsA[lkq + 1][lm] = bA4.y;
        BsA[lkq + 2][lm] = bA4.z; BsA[lkq + 3][lm] = bA4.w;
        __syncthreads();
        #pragma unroll
        for (int k = 0; k < 16; k++) {
            float4 avA = *(float4*)&AsA[k][ty * 4];
            float4 avH = *(float4*)&AsH[k][ty * 4];
            float4 bvH = *(float4*)&BsH[k][tx * 4];
            float4 bvA = *(float4*)&BsA[k][tx * 4];
            unsigned long long h01 = pk2(bvH.x, bvH.y);
            unsigned long long h23 = pk2(bvH.z, bvH.w);
            unsigned long long A01 = pk2(bvA.x, bvA.y);
            unsigned long long A23 = pk2(bvA.z, bvA.w);
            float amA[4] = {avA.x, avA.y, avA.z, avA.w};
            float amH[4] = {avH.x, avH.y, avH.z, avH.w};
            #pragma unroll
            for (int i = 0; i < 4; i++) {
                unsigned long long dA = dup2(amA[i]);
                unsigned long long dH = dup2(amH[i]);
                fma2(accp[i][0], dA, h01);
                fma2(accp[i][1], dA, h23);
                fma2(accp[i][0], dH, A01);
                fma2(accp[i][1], dH, A23);
            }
        }
        __syncthreads();
    }
    #pragma unroll
    for (int i = 0; i < 4; i++) {
        int m = m0 + ty * 4 + i, n = n0 + tx * 4;
        float2 c01 = unpk(accp[i][0]);
        float2 c23 = unpk(accp[i][1]);
        float4 ad = *(const float4*)&Adj[(long)m * N + n];
        float4 v;
        v.x = (ad.x > 0.f) ? c01.x : -9e15f;
        v.y = (ad.y > 0.f) ? c01.y : -9e15f;
        v.z = (ad.z > 0.f) ? c23.x : -9e15f;
        v.w = (ad.w > 0.f) ? c23.y : -9e15f;
        *(float4*)&Cb[(long)m * N + n] = v;
    }
}

// row softmax of the symmetric masked logits (== column softmax transposed)
// bx < 4096: graph2 row (512 wide); else graph1 row (128 wide)
__global__ void k_rowsm(const float* __restrict__ e2, float* __restrict__ a2,
                        const float* __restrict__ e1, float* __restrict__ a1) {
    int bx = blockIdx.x;
    int t = threadIdx.x;
    int lane = t & 31, w = t >> 5;
    __shared__ float red[4];
    __shared__ float bcast;
    if (bx < BB * NN2) {
        const float* L = e2 + (long)bx * NN2;
        float* O = a2 + (long)bx * NN2;
        float v[4];
        float m = -3.4e38f;
        #pragma unroll
        for (int q = 0; q < 4; q++) { v[q] = L[t + 128 * q]; m = fmaxf(m, v[q]); }
        #pragma unroll
        for (int o = 16; o > 0; o >>= 1) m = fmaxf(m, __shfl_xor_sync(0xffffffffu, m, o));
        if (lane == 0) red[w] = m;
        __syncthreads();
        if (t == 0) bcast = fmaxf(fmaxf(red[0], red[1]), fmaxf(red[2], red[3]));
        __syncthreads();
        m = bcast;
        float s = 0.f;
        #pragma unroll
        for (int q = 0; q < 4; q++) { v[q] = __expf(v[q] - m); s += v[q]; }
        #pragma unroll
        for (int o = 16; o > 0; o >>= 1) s += __shfl_xor_sync(0xffffffffu, s, o);
        if (lane == 0) red[w] = s;
        __syncthreads();
        if (t == 0) bcast = red[0] + red[1] + red[2] + red[3];
        __syncthreads();
        float inv = 1.f / bcast;
        #pragma unroll
        for (int q = 0; q < 4; q++) O[t + 128 * q] = v[q] * inv;
    } else {
        int row = bx - BB * NN2;
        const float* L = e1 + (long)row * NN1;
        float* O = a1 + (long)row * NN1;
        float v = L[t];
        float m = v;
        #pragma unroll
        for (int o = 16; o > 0; o >>= 1) m = fmaxf(m, __shfl_xor_sync(0xffffffffu, m, o));
        if (lane == 0) red[w] = m;
        __syncthreads();
        if (t == 0) bcast = fmaxf(fmaxf(red[0], red[1]), fmaxf(red[2], red[3]));
        __syncthreads();
        m = bcast;
        float e = __expf(v - m);
        float s = e;
        #pragma unroll
        for (int o = 16; o > 0; o >>= 1) s += __shfl_xor_sync(0xffffffffu, s, o);
        if (lane == 0) red[w] = s;
        __syncthreads();
        if (t == 0) bcast = red[0] + red[1] + red[2] + red[3];
        __syncthreads();
        O[t] = e / bcast;
    }
}

// split-K hp GEMM (TN: hp = R^T @ h): part[chunk][i,d] = sum_{k in chunk} R[k,i] h[k,d]
// z<8 graph2 (K=512 in 4 chunks of 128), z>=8 graph1 (K=128, 1 chunk)
__global__ void k_hp(const float* __restrict__ a2, const float* __restrict__ a1,
                     const float* __restrict__ h, float* __restrict__ part) {
    int z = blockIdx.z;
    if (z < 8) {
        int chunk = blockIdx.x >> 1, nt = blockIdx.x & 1;
        const float* A = a2 + (long)z * NN2 * NN2 + (long)chunk * 128 * NN2;  // rows k
        const float* B = h + ((long)R1 + (long)z * NN2 + chunk * 128) * DD;
        float* C = part + (long)chunk * MROWS * DD + ((long)R1 + (long)z * NN2) * DD;
        gemm64tn(A, NN2, B, DD, C, DD, 128, blockIdx.y * 64, nt * 64);
    } else {
        if (blockIdx.x >= 2 || blockIdx.y >= 2) return;
        const float* A = a1 + (long)(z - 8) * NN1 * NN1;
        const float* B = h + (long)(z - 8) * NN1 * DD;
        float* C = part + (long)(z - 8) * NN1 * DD;
        gemm64tn(A, NN1, B, DD, C, DD, NN1, blockIdx.y * 64, blockIdx.x * 64);
    }
}

// gate: hp = relu(sum chunks); c = sigmoid(g.gW1 + hp.gW2 + gb); g = c*g + (1-c)*hp
__global__ void k_gate(float* __restrict__ g, const float* __restrict__ part,
                       const float* __restrict__ gW, const float* __restrict__ gb) {
    long row = blockIdx.x;
    int t = threadIdx.x;
    float hp = part[row * DD + t];
    if (row >= R1) {
        hp += part[(long)1 * MROWS * DD + row * DD + t];
        hp += part[(long)2 * MROWS * DD + row * DD + t];
        hp += part[(long)3 * MROWS * DD + row * DD + t];
    }
    hp = fmaxf(hp, 0.f);
    float x = g[row * DD + t];
    float v = x * gW[t] + hp * gW[DD + t];
    #pragma unroll
    for (int o = 16; o > 0; o >>= 1) v += __shfl_down_sync(0xffffffffu, v, o);
    __shared__ float red[4];
    __shared__ float csh;
    if ((t & 31) == 0) red[t >> 5] = v;
    __syncthreads();
    if (t == 0) {
        float s = red[0] + red[1] + red[2] + red[3] + gb[0];
        csh = 1.f / (1.f + __expf(-s));
    }
    __syncthreads();
    float c = csh;
    g[row * DD + t] = c * x + (1.f - c) * hp;
}

// all 4 pair projections in one launch (z: 0=p1a 1=p1b 2=p2a 3=p2b)
__global__ void k_proj(const float* __restrict__ g,
                       const float* __restrict__ WA1, const float* __restrict__ bA1,
                       const float* __restrict__ WB1, const float* __restrict__ bB1,
                       float* __restrict__ p1a, float* __restrict__ p1b,
                       float* __restrict__ p2a, float* __restrict__ p2b) {
    int z = blockIdx.z;
    const float* A; const float* B; const float* bias; float* C; int mt;
    switch (z) {
        case 0: A = g;            B = WA1;           bias = bA1;   C = p1a; mt = R1 / 64; break;
        case 1: A = g;            B = WB1;           bias = bB1;   C = p1b; mt = R1 / 64; break;
        case 2: A = g + (long)R1 * DD; B = WA1 + DD * DD; bias = nullptr; C = p2a; mt = (BB * NN2) / 64; break;
        default:A = g + (long)R1 * DD; B = WB1 + DD * DD; bias = nullptr; C = p2b; mt = (BB * NN2) / 64; break;
    }
    if ((int)blockIdx.y >= mt) return;
    gemm64k(A, DD, B, DD, bias, C, DD, DD, blockIdx.y * 64, blockIdx.x * 64);
}

// Z[b,i,j] = act( b2 + sum_h relu(P1[i,h]+P2[j,h]) * w2[h] ), 32x32 tiles
__global__ void k_zmat(const float* __restrict__ p1a, const float* __restrict__ p1b,
                       const float* __restrict__ p2a, const float* __restrict__ p2b,
                       const float* __restrict__ w2A, const float* __restrict__ w2B,
                       const float* __restrict__ b2A, const float* __restrict__ b2B,
                       float* __restrict__ ZA, float* __restrict__ ZB) {
    __shared__ float P1s[DD][33];
    __shared__ float P2s[DD][33];
    __shared__ float w2s[DD];
    int z = blockIdx.z;
    int b = z >> 1, mlp = z & 1;
    const float* P1 = (mlp ? p1b : p1a) + (long)b * NN1 * DD;
    const float* P2 = (mlp ? p2b : p2a) + (long)b * NN2 * DD;
    const float* w2 = mlp ? w2B : w2A;
    float b2 = mlp ? b2B[0] : b2A[0];
    float* Z = (mlp ? ZB : ZA) + (long)b * NN1 * NN2;
    int i0 = blockIdx.y * 32, j0 = blockIdx.x * 32;
    int tid = threadIdx.x;
    if (tid < DD) w2s[tid] = w2[tid];
    {
        int row = tid >> 3, cb = (tid & 7) * 16;
        #pragma unroll
        for (int q = 0; q < 4; q++) {
            float4 v1 = *(const float4*)&P1[(long)(i0 + row) * DD + cb + q * 4];
            float4 v2 = *(const float4*)&P2[(long)(j0 + row) * DD + cb + q * 4];
            P1s[cb + q * 4 + 0][row] = v1.x; P1s[cb + q * 4 + 1][row] = v1.y;
            P1s[cb + q * 4 + 2][row] = v1.z; P1s[cb + q * 4 + 3][row] = v1.w;
            P2s[cb + q * 4 + 0][row] = v2.x; P2s[cb + q * 4 + 1][row] = v2.y;
            P2s[cb + q * 4 + 2][row] = v2.z; P2s[cb + q * 4 + 3][row] = v2.w;
        }
    }
    __syncthreads();
    int tx = tid & 15, ty = tid >> 4;
    float a00 = 0.f, a01 = 0.f, a10 = 0.f, a11 = 0.f;
    #pragma unroll 4
    for (int k = 0; k < DD; k++) {
        float w = w2s[k];
        float p0 = P1s[k][ty], p1 = P1s[k][ty + 16];
        float q0 = P2s[k][tx], q1 = P2s[k][tx + 16];
        a00 += fmaxf(p0 + q0, 0.f) * w;
        a01 += fmaxf(p0 + q1, 0.f) * w;
        a10 += fmaxf(p1 + q0, 0.f) * w;
        a11 += fmaxf(p1 + q1, 0.f) * w;
    }
    a00 += b2; a01 += b2; a10 += b2; a11 += b2;
    if (mlp == 0) {
        a00 = 1.f / (1.f + __expf(-a00)); a01 = 1.f / (1.f + __expf(-a01));
        a10 = 1.f / (1.f + __expf(-a10)); a11 = 1.f / (1.f + __expf(-a11));
    } else {
        a00 = tanhf(a00) * 0.2f; a01 = tanhf(a01) * 0.2f;
        a10 = tanhf(a10) * 0.2f; a11 = tanhf(a11) * 0.2f;
    }
    Z[(long)(i0 + ty) * NN2 + j0 + tx]           = a00;
    Z[(long)(i0 + ty) * NN2 + j0 + tx + 16]      = a01;
    Z[(long)(i0 + ty + 16) * NN2 + j0 + tx]      = a10;
    Z[(long)(i0 + ty + 16) * NN2 + j0 + tx + 16] = a11;
}

// elementwise physics + per-(b,i) reduction
__global__ void k_phys(const float* __restrict__ ZA, const float* __restrict__ ZB,
                       const float* __restrict__ pos1, const float* __restrict__ pos2,
                       const float* __restrict__ r1, const float* __restrict__ r2,
                       const float* __restrict__ nm1, const float* __restrict__ nm2,
                       const float* __restrict__ A_int, float* __restrict__ part) {
    int b = blockIdx.x >> 7, i = blockIdx.x & 127;
    int t = threadIdx.x;
    float px = pos1[(b * NN1 + i) * 3 + 0];
    float py = pos1[(b * NN1 + i) * 3 + 1];
    float pz = pos1[(b * NN1 + i) * 3 + 2];
    float rr1 = r1[b * NN1 + i];
    float m1  = nm1[b * NN1 + i];
    size_t zbase = (size_t)b * NN1 * NN2 + (size_t)i * NN2;
    size_t abase = (size_t)b * 8 * NN1 * NN2 + (size_t)i * NN2;
    const size_t chw = (size_t)NN1 * NN2;
    float s0 = 0.f, s1 = 0.f, s2 = 0.f, s3 = 0.f;
    for (int j = t; j < NN2; j += 128) {
        float Aw = ZA[zbase + j];
        float Bw = ZB[zbase + j];
        float dx = px - pos2[(b * NN2 + j) * 3 + 0];
        float dy = py - pos2[(b * NN2 + j) * 3 + 1];
        float dz = pz - pos2[(b * NN2 + j) * 3 + 2];
        float dm = sqrtf(dx * dx + dy * dy + dz * dz + 1e-10f);
        if (dm < 0.5f) dm = 1e10f;
        float dm0 = rr1 + r2[b * NN2 + j] + Bw;
        float dm0s = (dm0 < 1e-4f) ? 1.f : dm0;
        float rq = dm0s / dm;
        float rq2 = rq * rq;
        float r6 = rq2 * rq2 * rq2;
        float evdw = fminf(r6 * r6 - 2.f * r6, 100.f);
        float Aamp = Aw * (0.0356f - 0.0178f) + 0.0178f;
        s0 += Aamp * evdw * m1 * nm2[b * NN2 + j];
        float dmd = dm - dm0;
        float a1 = A_int[abase + 1 * chw + j];
        float a7 = A_int[abase + 7 * chw + j];
        float a6 = A_int[abase + 6 * chw + j];
        s1 += fminf(fmaxf(dmd * a1 * (-1.f / 0.7f), 0.f), 1.f);
        s2 += fminf(fmaxf(dmd * a7 * (-1.f / 0.7f), 0.f), 1.f);
        s3 += fminf(fmaxf((1.5f - dmd) * a6, 0.f), 1.f);
    }
    #pragma unroll
    for (int o = 16; o > 0; o >>= 1) {
        s0 += __shfl_down_sync(0xffffffffu, s0, o);
        s1 += __shfl_down_sync(0xffffffffu, s1, o);
        s2 += __shfl_down_sync(0xffffffffu, s2, o);
        s3 += __shfl_down_sync(0xffffffffu, s3, o);
    }
    __shared__ float acc[4][4];
    int lane = t & 31, w = t >> 5;
    if (lane == 0) { acc[w][0] = s0; acc[w][1] = s1; acc[w][2] = s2; acc[w][3] = s3; }
    __syncthreads();
    if (t < 4)
        part[((size_t)b * NN1 + i) * 4 + t] = acc[0][t] + acc[1][t] + acc[2][t] + acc[3][t];
}

__global__ void k_final(const float* __restrict__ part, const float* __restrict__ rotor,
                        const float* __restrict__ duff, const float* __restrict__ hbc,
                        const float* __restrict__ hyc, const float* __restrict__ vdc,
                        const float* __restrict__ rtc, float* __restrict__ out) {
    int b = blockIdx.x, t = threadIdx.x;
    size_t base = ((size_t)b * NN1 + t) * 4;
    float v0 = part[base + 0], v1 = part[base + 1], v2 = part[base + 2], v3 = part[base + 3];
    #pragma unroll
    for (int o = 16; o > 0; o >>= 1) {
        v0 += __shfl_down_sync(0xffffffffu, v0, o);
        v1 += __shfl_down_sync(0xffffffffu, v1, o);
        v2 += __shfl_down_sync(0xffffffffu, v2, o);
        v3 += __shfl_down_sync(0xffffffffu, v3, o);
    }
    __shared__ float red[4][4];
    if ((t & 31) == 0) {
        int w = t >> 5;
        red[w][0] = v0; red[w][1] = v1; red[w][2] = v2; red[w][3] = v3;
    }
    __syncthreads();
    if (t == 0) {
        float s0 = red[0][0] + red[1][0] + red[2][0] + red[3][0];
        float s1 = red[0][1] + red[1][1] + red[2][1] + red[3][1];
        float s2 = red[0][2] + red[1][2] + red[2][2] + red[3][2];
        float s3 = red[0][3] + red[1][3] + red[2][3] + red[3][3];
        float hb = -hbc[0] * hbc[0];
        float hy = -hyc[0] * hyc[0];
        float inv = 1.f / (1.f + rtc[0] * rtc[0] * rotor[b]);
        out[b * 5 + 0] = s0 * inv;
        out[b * 5 + 1] = s1 * hb * inv;
        out[b * 5 + 2] = s2 * hb * inv;
        out[b * 5 + 3] = s3 * hy * inv;
        out[b * 5 + 4] = duff[b] * vdc[0] * vdc[0] * inv;
    }
}

// ---------------- host side ----------------
extern "C" void kernel_launch(void* const* d_in, const int* in_sizes, int n_in,
                              void* d_out, int out_size) {
    (void)in_sizes; (void)n_in; (void)out_size;
    const float* h1      = (const float*)d_in[0];
    const float* adj1    = (const float*)d_in[1];
    const float* h2      = (const float*)d_in[2];
    const float* adj2    = (const float*)d_in[3];
    const float* A_int   = (const float*)d_in[4];
    const float* pos1    = (const float*)d_in[5];
    const float* pos2    = (const float*)d_in[6];
    const float* rotor   = (const float*)d_in[7];
    const float* vdw_r1  = (const float*)d_in[8];
    const float* vdw_r2  = (const float*)d_in[9];
    const float* duff    = (const float*)d_in[10];
    const float* nm1     = (const float*)d_in[11];
    const float* nm2     = (const float*)d_in[12];
    const float* node_W  = (const float*)d_in[13];
    const float* gat_W   = (const float*)d_in[14];
    const float* gat_b   = (const float*)d_in[15];
    const float* gat_A   = (const float*)d_in[16];
    const float* gate_W  = (const float*)d_in[17];
    const float* gate_b  = (const float*)d_in[18];
    const float* vdwA_W1 = (const float*)d_in[19];
    const float* vdwA_b1 = (const float*)d_in[20];
    const float* vdwA_W2 = (const float*)d_in[21];
    const float* vdwA_b2 = (const float*)d_in[22];
    const float* vdwB_W1 = (const float*)d_in[23];
    const float* vdwB_b1 = (const float*)d_in[24];
    const float* vdwB_W2 = (const float*)d_in[25];
    const float* vdwB_b2 = (const float*)d_in[26];
    const float* hbond   = (const float*)d_in[27];
    const float* hydro   = (const float*)d_in[28];
    const float* vdwc    = (const float*)d_in[29];
    const float* rotc    = (const float*)d_in[30];
    float* out = (float*)d_out;

    float *gp, *hp_, *hAp, *hpart, *e2p, *a2p, *e1p, *a1p, *wap, *bap;
    float *p1a, *p1b, *p2a, *p2b, *zap, *zbp, *partp;
    cudaGetSymbolAddress((void**)&gp,  g_g);
    cudaGetSymbolAddress((void**)&hp_, g_h);
    cudaGetSymbolAddress((void**)&hAp, g_hA);
    cudaGetSymbolAddress((void**)&hpart, g_hpart);
    cudaGetSymbolAddress((void**)&e2p, g_e2);
    cudaGetSymbolAddress((void**)&a2p, g_a2);
    cudaGetSymbolAddress((void**)&e1p, g_e1);
    cudaGetSymbolAddress((void**)&a1p, g_a1);
    cudaGetSymbolAddress((void**)&wap, g_WA);
    cudaGetSymbolAddress((void**)&bap, g_bA);
    cudaGetSymbolAddress((void**)&p1a, g_P1A);
    cudaGetSymbolAddress((void**)&p1b, g_P1B);
    cudaGetSymbolAddress((void**)&p2a, g_P2A);
    cudaGetSymbolAddress((void**)&p2b, g_P2B);
    cudaGetSymbolAddress((void**)&zap, g_ZA);
    cudaGetSymbolAddress((void**)&zbp, g_ZB);
    cudaGetSymbolAddress((void**)&partp, g_part);

    // precompute WA, bA; embedding
    k_wa<<<dim3(2, 2, 3), 256>>>(gat_W, gat_A, wap);
    k_bvec<<<3, DD>>>(gat_b, gat_A, bap);
    k_embed_both<<<MROWS, DD>>>(h1, h2, node_W, gp);

    for (int l = 0; l < 3; l++) {
        const float* W  = gat_W  + (size_t)l * DD * DD;
        const float* bW = gat_b  + (size_t)l * DD;
        const float* WA = wap    + (size_t)l * DD * DD;
        const float* bA = bap    + (size_t)l * DD;
        const float* gW = gate_W + (size_t)l * 2 * DD;
        const float* gb = gate_b + l;
        k_dual<<<dim3(4, MROWS / 64, 1), 256>>>(gp, W, bW, WA, bA, hp_, hAp);
        k_ntsym<<<dim3(8, 8, 16), 256>>>(hp_, hAp, adj2, e2p, adj1, e1p);
        k_rowsm<<<BB * NN2 + BB * NN1, 128>>>(e2p, a2p, e1p, a1p);
        k_hp<<<dim3(8, 8, 16), 256>>>(a2p, a1p, hp_, hpart);
        k_gate<<<MROWS, DD>>>(gp, hpart, gW, gb);
    }

    // pair projections (one launch)
    k_proj<<<dim3(2, 64, 4), 256>>>(gp, vdwA_W1, vdwA_b1, vdwB_W1, vdwB_b1,
                                    p1a, p1b, p2a, p2b);
    // pair bilinear-relu MLP matrices
    k_zmat<<<dim3(16, 4, 16), 256>>>(p1a, p1b, p2a, p2b, vdwA_W2, vdwB_W2,
                                     vdwA_b2, vdwB_b2, zap, zbp);
    // physics + reductions
    k_phys<<<BB * NN1, 128>>>(zap, zbp, pos1, pos2, vdw_r1, vdw_r2, nm1, nm2,
                              A_int, partp);
    k_final<<<BB, 128>>>(partp, rotor, duff, hbond, hydro, vdwc, rotc, out);
}